// round 1
// baseline (speedup 1.0000x reference)
#include <cuda_runtime.h>

#define NODES 50000
#define EDIM 128
#define PDIM 768
#define HID 256
#define NREL 16
#define NEDGE 400000
#define BN_EPS 1e-5f

// ---------------- scratch (static device memory; no allocations) ----------------
__device__ float g_xn[NODES * EDIM];        // normalized embeddings
__device__ float g_x0[NODES * PDIM];        // projected features (layer0 input)
__device__ float g_h0[NODES * HID];         // x @ bases[0]
__device__ float g_h1[NODES * HID];         // x @ bases[1]
__device__ float g_buf[NODES * HID];        // conv output (x@root + bias + agg)
__device__ float g_x1[NODES * HID];         // layer output (BN+ReLU)
__device__ int   g_cnt[NODES * NREL];       // per-(dst,rel) edge counts
__device__ float g_invd[NEDGE];             // 1/max(cnt,1) per edge
__device__ float g_sum[HID];
__device__ float g_sumsq[HID];
__device__ float g_scale[HID];
__device__ float g_shift[HID];

// ---------------- row L2-normalize emb -> g_xn ----------------
__global__ void norm_rows(const float* __restrict__ emb) {
    int gw = (blockIdx.x * blockDim.x + threadIdx.x) >> 5;
    if (gw >= NODES) return;
    int lane = threadIdx.x & 31;
    float4 v = ((const float4*)(emb + (size_t)gw * EDIM))[lane];
    float ss = v.x * v.x + v.y * v.y + v.z * v.z + v.w * v.w;
#pragma unroll
    for (int o = 16; o > 0; o >>= 1) ss += __shfl_xor_sync(0xffffffffu, ss, o);
    float inv = 1.0f / fmaxf(sqrtf(ss), 1e-12f);
    v.x *= inv; v.y *= inv; v.z *= inv; v.w *= inv;
    ((float4*)(g_xn + (size_t)gw * EDIM))[lane] = v;
}

// ---------------- SIMT fp32 GEMM: C[z] = A @ B[z] (+bias[z]) ----------------
// 128x128 tile, BK=8, 256 threads, 8x8 microtile per thread.
__global__ void __launch_bounds__(256) gemm3(
    const float* __restrict__ A, int M, int K, int N,
    const float* __restrict__ B0, const float* __restrict__ B1, const float* __restrict__ B2,
    float* C0, float* C1, float* C2,
    const float* __restrict__ bias0, const float* __restrict__ bias1, const float* __restrict__ bias2)
{
    const int z = blockIdx.z;
    const float* __restrict__ B = (z == 0) ? B0 : (z == 1) ? B1 : B2;
    float* C = (z == 0) ? C0 : (z == 1) ? C1 : C2;
    const float* bias = (z == 0) ? bias0 : (z == 1) ? bias1 : bias2;

    __shared__ float As[8][132];   // transposed A tile: As[k][m], pad keeps 16B align + no conflicts
    __shared__ float Bs[8][132];   // Bs[k][n]

    const int t = threadIdx.x;
    const int tx = t & 15, ty = t >> 4;
    const int tx4 = tx * 4, ty4 = ty * 4;
    const int row0 = blockIdx.y * 128;
    const int n0 = blockIdx.x * 128;

    const int ar = t >> 1, ac4 = (t & 1) * 4;     // A tile load map (128 rows x 8 cols)
    const int bk = t >> 5, bc4 = (t & 31) * 4;    // B tile load map (8 rows x 128 cols)

    float acc[8][8];
#pragma unroll
    for (int i = 0; i < 8; i++)
#pragma unroll
        for (int j = 0; j < 8; j++) acc[i][j] = 0.0f;

    for (int k0 = 0; k0 < K; k0 += 8) {
        float4 av = make_float4(0.f, 0.f, 0.f, 0.f);
        if (row0 + ar < M)
            av = *(const float4*)(A + (size_t)(row0 + ar) * K + k0 + ac4);
        float4 bv = *(const float4*)(B + (size_t)(k0 + bk) * N + n0 + bc4);
        __syncthreads();
        As[ac4 + 0][ar] = av.x;
        As[ac4 + 1][ar] = av.y;
        As[ac4 + 2][ar] = av.z;
        As[ac4 + 3][ar] = av.w;
        *(float4*)&Bs[bk][bc4] = bv;
        __syncthreads();
#pragma unroll
        for (int k = 0; k < 8; k++) {
            float a[8], b[8];
            *(float4*)&a[0] = *(const float4*)&As[k][ty4];
            *(float4*)&a[4] = *(const float4*)&As[k][ty4 + 64];
            *(float4*)&b[0] = *(const float4*)&Bs[k][tx4];
            *(float4*)&b[4] = *(const float4*)&Bs[k][tx4 + 64];
#pragma unroll
            for (int i = 0; i < 8; i++)
#pragma unroll
                for (int j = 0; j < 8; j++)
                    acc[i][j] = fmaf(a[i], b[j], acc[i][j]);
        }
    }

    float4 bb[2] = { make_float4(0, 0, 0, 0), make_float4(0, 0, 0, 0) };
    if (bias) {
        bb[0] = *(const float4*)(bias + n0 + tx4);
        bb[1] = *(const float4*)(bias + n0 + 64 + tx4);
    }
#pragma unroll
    for (int ih = 0; ih < 2; ih++)
#pragma unroll
        for (int i = 0; i < 4; i++) {
            int r = row0 + ih * 64 + ty4 + i;
            if (r >= M) continue;
#pragma unroll
            for (int jh = 0; jh < 2; jh++) {
                float4 o;
                o.x = acc[ih * 4 + i][jh * 4 + 0] + bb[jh].x;
                o.y = acc[ih * 4 + i][jh * 4 + 1] + bb[jh].y;
                o.z = acc[ih * 4 + i][jh * 4 + 2] + bb[jh].z;
                o.w = acc[ih * 4 + i][jh * 4 + 3] + bb[jh].w;
                *(float4*)(C + (size_t)r * N + n0 + jh * 64 + tx4) = o;
            }
        }
}

// ---------------- edge denominator precompute ----------------
__global__ void zero_cnt() {
    int i = blockIdx.x * blockDim.x + threadIdx.x;
    if (i < NODES * NREL) g_cnt[i] = 0;
}

__global__ void count_edges(const int* __restrict__ dst, const int* __restrict__ et) {
    int e = blockIdx.x * blockDim.x + threadIdx.x;
    if (e < NEDGE) atomicAdd(&g_cnt[dst[e] * NREL + et[e]], 1);
}

__global__ void compute_invd(const int* __restrict__ dst, const int* __restrict__ et) {
    int e = blockIdx.x * blockDim.x + threadIdx.x;
    if (e < NEDGE) {
        int c = g_cnt[dst[e] * NREL + et[e]];
        g_invd[e] = 1.0f / (float)(c > 0 ? c : 1);
    }
}

// ---------------- edge aggregation: g_buf[dst] += invd*(c0*h0[src] + c1*h1[src]) ----------------
__global__ void edge_agg(const int* __restrict__ src, const int* __restrict__ dst,
                         const int* __restrict__ et, const float* __restrict__ comp) {
    int gw = (blockIdx.x * blockDim.x + threadIdx.x) >> 5;
    if (gw >= NEDGE) return;
    int lane = threadIdx.x & 31;
    int s = src[gw], d = dst[gw], r = et[gw];
    float w = g_invd[gw];
    float c0 = comp[r * 2 + 0] * w;
    float c1 = comp[r * 2 + 1] * w;
    const float4* p0 = (const float4*)&g_h0[(size_t)s * HID];
    const float4* p1 = (const float4*)&g_h1[(size_t)s * HID];
    float* po = &g_buf[(size_t)d * HID];
#pragma unroll
    for (int i = 0; i < 2; i++) {
        int c = lane + i * 32;          // float4 index 0..63
        float4 a = p0[c], b = p1[c];
        atomicAdd(&po[c * 4 + 0], fmaf(c0, a.x, c1 * b.x));
        atomicAdd(&po[c * 4 + 1], fmaf(c0, a.y, c1 * b.y));
        atomicAdd(&po[c * 4 + 2], fmaf(c0, a.z, c1 * b.z));
        atomicAdd(&po[c * 4 + 3], fmaf(c0, a.w, c1 * b.w));
    }
}

// ---------------- batchnorm ----------------
__global__ void zero_stats() {
    int c = threadIdx.x;
    g_sum[c] = 0.f;
    g_sumsq[c] = 0.f;
}

__global__ void bn_stats() {
    int c = threadIdx.x;
    float s = 0.f, ss = 0.f;
    for (int r = blockIdx.x; r < NODES; r += gridDim.x) {
        float v = g_buf[(size_t)r * HID + c];
        s += v;
        ss += v * v;
    }
    atomicAdd(&g_sum[c], s);
    atomicAdd(&g_sumsq[c], ss);
}

__global__ void bn_finalize(const float* __restrict__ gamma, const float* __restrict__ beta) {
    int c = threadIdx.x;
    const float invM = 1.0f / (float)NODES;
    float mean = g_sum[c] * invM;
    float var = g_sumsq[c] * invM - mean * mean;
    float sc = gamma[c] * rsqrtf(var + BN_EPS);
    g_scale[c] = sc;
    g_shift[c] = beta[c] - mean * sc;
}

__global__ void bn_apply(float* __restrict__ out) {
    int idx = blockIdx.x * blockDim.x + threadIdx.x;   // float4 index
    if (idx >= NODES * HID / 4) return;
    int c4 = (idx & 63) << 2;
    float4 v = ((const float4*)g_buf)[idx];
    float4 sc = *(const float4*)&g_scale[c4];
    float4 sh = *(const float4*)&g_shift[c4];
    v.x = fmaxf(fmaf(v.x, sc.x, sh.x), 0.f);
    v.y = fmaxf(fmaf(v.y, sc.y, sh.y), 0.f);
    v.z = fmaxf(fmaf(v.z, sc.z, sh.z), 0.f);
    v.w = fmaxf(fmaf(v.w, sc.w, sh.w), 0.f);
    ((float4*)out)[idx] = v;
}

// ---------------- host launch ----------------
extern "C" void kernel_launch(void* const* d_in, const int* in_sizes, int n_in,
                              void* d_out, int out_size) {
    const int* edge_index = (const int*)d_in[0];
    const int* src = edge_index;
    const int* dst = edge_index + NEDGE;
    const int* etype = (const int*)d_in[1];
    const float* emb = (const float*)d_in[2];
    const float* proj_w = (const float*)d_in[3];
    const float* proj_b = (const float*)d_in[4];

    const float *comp[3], *bases[3], *root[3], *bias[3], *gamma[3], *beta[3];
    for (int l = 0; l < 3; l++) {
        comp[l]  = (const float*)d_in[5 + 6 * l];
        bases[l] = (const float*)d_in[6 + 6 * l];
        root[l]  = (const float*)d_in[7 + 6 * l];
        bias[l]  = (const float*)d_in[8 + 6 * l];
        gamma[l] = (const float*)d_in[9 + 6 * l];
        beta[l]  = (const float*)d_in[10 + 6 * l];
    }

    float *xn, *x0, *h0, *h1, *buf, *x1;
    cudaGetSymbolAddress((void**)&xn, g_xn);
    cudaGetSymbolAddress((void**)&x0, g_x0);
    cudaGetSymbolAddress((void**)&h0, g_h0);
    cudaGetSymbolAddress((void**)&h1, g_h1);
    cudaGetSymbolAddress((void**)&buf, g_buf);
    cudaGetSymbolAddress((void**)&x1, g_x1);

    const int MBLK = (NODES + 127) / 128;   // 391

    // normalize + projection
    norm_rows<<<(NODES * 32 + 255) / 256, 256>>>(emb);
    {
        dim3 grid(PDIM / 128, MBLK, 1);
        gemm3<<<grid, 256>>>(xn, NODES, EDIM, PDIM,
                             proj_w, proj_w, proj_w,
                             x0, x0, x0,
                             proj_b, proj_b, proj_b);
    }

    // per-(dst,rel) mean denominators (shared by all layers)
    zero_cnt<<<(NODES * NREL + 255) / 256, 256>>>();
    count_edges<<<(NEDGE + 255) / 256, 256>>>(dst, etype);
    compute_invd<<<(NEDGE + 255) / 256, 256>>>(dst, etype);

    for (int l = 0; l < 3; l++) {
        const float* x = (l == 0) ? x0 : x1;
        int K = (l == 0) ? PDIM : HID;

        // h0 = x@bases[0], h1 = x@bases[1], buf = x@root + bias
        dim3 grid(HID / 128, MBLK, 3);
        gemm3<<<grid, 256>>>(x, NODES, K, HID,
                             bases[l], bases[l] + (size_t)K * HID, root[l],
                             h0, h1, buf,
                             (const float*)nullptr, (const float*)nullptr, bias[l]);

        // buf += scatter-mean messages
        edge_agg<<<NEDGE / 8, 256>>>(src, dst, etype, comp[l]);

        // batchnorm + relu
        zero_stats<<<1, HID>>>();
        bn_stats<<<256, HID>>>();
        bn_finalize<<<1, HID>>>(gamma[l], beta[l]);
        float* outp = (l == 2) ? (float*)d_out : x1;
        bn_apply<<<(NODES * HID / 4 + 255) / 256, 256>>>(outp);
    }
}

// round 3
// speedup vs baseline: 1.5708x; 1.5708x over previous
#include <cuda_runtime.h>
#include <cuda_bf16.h>
#include <cstdint>

#define NODES 50000
#define MPAD  50048
#define EDIM  128
#define PDIM  768
#define HID   256
#define NREL  16
#define NEDGE 400000
#define BN_EPS 1e-5f
#define MBLK  391          // 50048/128

// ---------------------------------------------------------------------------
// scratch (static device memory; no allocations)
// ---------------------------------------------------------------------------
__device__ __nv_bfloat16 g_Ah0[(size_t)MPAD * PDIM];
__device__ __nv_bfloat16 g_Al0[(size_t)MPAD * PDIM];
__device__ __nv_bfloat16 g_Ah1[(size_t)MPAD * PDIM];
__device__ __nv_bfloat16 g_Al1[(size_t)MPAD * PDIM];
__device__ __nv_bfloat16 g_Bth[3 * 256 * 768];          // split-B^T (K-major, [N,K])
__device__ __nv_bfloat16 g_Btl[3 * 256 * 768];
__device__ float g_h0[(size_t)MPAD * HID];
__device__ float g_h1[(size_t)MPAD * HID];
__device__ float g_buf[(size_t)MPAD * HID];
__device__ int   g_cnt[NODES * NREL];
__device__ float g_invd[NEDGE];
__device__ float g_sum[HID], g_sumsq[HID], g_scale[HID], g_shift[HID];

// ---------------------------------------------------------------------------
// helpers
// ---------------------------------------------------------------------------
__device__ __forceinline__ uint32_t smem_u32(const void* p) {
    uint32_t a;
    asm("{ .reg .u64 t; cvta.to.shared.u64 t, %1; cvt.u32.u64 %0, t; }" : "=r"(a) : "l"(p));
    return a;
}
__device__ __forceinline__ void cp16(uint32_t dst, const void* src) {
    asm volatile("cp.async.cg.shared.global [%0], [%1], 16;" :: "r"(dst), "l"(src) : "memory");
}
__device__ __forceinline__ void ldsm4(uint32_t* r, uint32_t addr) {
    asm volatile("ldmatrix.sync.aligned.m8n8.x4.shared.b16 {%0,%1,%2,%3}, [%4];"
                 : "=r"(r[0]), "=r"(r[1]), "=r"(r[2]), "=r"(r[3]) : "r"(addr));
}
__device__ __forceinline__ void mma16816(float* c, const uint32_t* a, const uint32_t* b) {
    asm volatile("mma.sync.aligned.m16n8k16.row.col.f32.bf16.bf16.f32 "
                 "{%0,%1,%2,%3}, {%4,%5,%6,%7}, {%8,%9}, {%0,%1,%2,%3};"
                 : "+f"(c[0]), "+f"(c[1]), "+f"(c[2]), "+f"(c[3])
                 : "r"(a[0]), "r"(a[1]), "r"(a[2]), "r"(a[3]), "r"(b[0]), "r"(b[1]));
}
static __device__ __forceinline__ uint32_t pack_bf2(float a, float b) {
    __nv_bfloat162 t;
    t.x = __float2bfloat16_rn(a);
    t.y = __float2bfloat16_rn(b);
    return *reinterpret_cast<uint32_t*>(&t);
}

// smem layout per stage: A_h | A_l | B_h | B_l, each 128 rows x 144B
#define ROWB   144
#define MATB   18432          // 128*144
#define STAGEB 73728          // 4*MATB
#define SMEM_GEMM (2 * STAGEB)

// ---------------------------------------------------------------------------
// split-bf16 GEMM via mma.sync: C = A @ B^T (+bias), CTA tile 128x128, K-chunk 64
// ---------------------------------------------------------------------------
__device__ __forceinline__ void load_stage(
    uint32_t sb, int stage, int k0,
    const __nv_bfloat16* __restrict__ Ah, const __nv_bfloat16* __restrict__ Al,
    const __nv_bfloat16* __restrict__ Bh, const __nv_bfloat16* __restrict__ Bl,
    int K, int t)
{
    uint32_t base = sb + stage * STAGEB;
    const __nv_bfloat16* srcs[4] = { Ah + k0, Al + k0, Bh + k0, Bl + k0 };
#pragma unroll
    for (int m = 0; m < 4; m++) {
        uint32_t sbase = base + m * MATB;
        const __nv_bfloat16* g = srcs[m];
#pragma unroll
        for (int i = 0; i < 4; i++) {
            int unit = t + i * 256;
            int r = unit >> 3, u = unit & 7;
            cp16(sbase + r * ROWB + u * 16, g + (size_t)r * K + u * 8);
        }
    }
    asm volatile("cp.async.commit_group;" ::: "memory");
}

__global__ void __launch_bounds__(256, 1) gemm_mma(
    const __nv_bfloat16* __restrict__ Ah, const __nv_bfloat16* __restrict__ Al,
    int K, int nbz,
    const __nv_bfloat16* __restrict__ Bth, const __nv_bfloat16* __restrict__ Btl,
    float* C0, float* C1, float* C2, int ldc,
    const float* bias0, const float* bias1, const float* bias2,
    __nv_bfloat16* Ch, __nv_bfloat16* Cl)
{
    extern __shared__ char smem[];
    uint32_t sb = smem_u32(smem);
    const int t = threadIdx.x;
    const int w = t >> 5, l = t & 31;
    const int wm = w >> 1, wn = w & 1;
    const int row0 = blockIdx.x * 128;
    const int col0 = blockIdx.y * 128;
    const int z = blockIdx.z;

    float* C = (z == 0) ? C0 : (z == 1) ? C1 : C2;
    const float* bias = (z == 0) ? bias0 : (z == 1) ? bias1 : bias2;

    const __nv_bfloat16* A_h = Ah + (size_t)row0 * K;
    const __nv_bfloat16* A_l = Al + (size_t)row0 * K;
    size_t Boff = (size_t)(z * nbz + blockIdx.y) * 128 * K;
    const __nv_bfloat16* B_h = Bth + Boff;
    const __nv_bfloat16* B_l = Btl + Boff;

    // ldmatrix per-lane offsets
    const uint32_t aoff = (uint32_t)((wm * 32 + (l & 15)) * ROWB + (l >> 4) * 16);
    const uint32_t boff = (uint32_t)((wn * 64 + (l & 7) + ((l >> 4) & 1) * 8) * ROWB
                                     + ((l >> 3) & 1) * 16);

    float acc[2][8][4];
#pragma unroll
    for (int mt = 0; mt < 2; mt++)
#pragma unroll
        for (int nt = 0; nt < 8; nt++)
#pragma unroll
            for (int j = 0; j < 4; j++) acc[mt][nt][j] = 0.f;

    const int nch = K >> 6;
    load_stage(sb, 0, 0, A_h, A_l, B_h, B_l, K, t);

    for (int c = 0; c < nch; c++) {
        if (c + 1 < nch) {
            load_stage(sb, (c + 1) & 1, (c + 1) << 6, A_h, A_l, B_h, B_l, K, t);
            asm volatile("cp.async.wait_group 1;" ::: "memory");
        } else {
            asm volatile("cp.async.wait_group 0;" ::: "memory");
        }
        __syncthreads();

        uint32_t Abase = sb + (c & 1) * STAGEB;
        uint32_t Bbase = Abase + 2 * MATB;
#pragma unroll
        for (int ks = 0; ks < 4; ks++) {
            uint32_t ah[2][4], al[2][4];
#pragma unroll
            for (int mt = 0; mt < 2; mt++) {
                ldsm4(ah[mt], Abase + aoff + mt * 2304 + ks * 32);
                ldsm4(al[mt], Abase + MATB + aoff + mt * 2304 + ks * 32);
            }
#pragma unroll
            for (int p = 0; p < 4; p++) {
                uint32_t bh[4], bl[4];
                ldsm4(bh, Bbase + boff + p * 2304 + ks * 32);
                ldsm4(bl, Bbase + MATB + boff + p * 2304 + ks * 32);
#pragma unroll
                for (int mt = 0; mt < 2; mt++)
#pragma unroll
                    for (int sub = 0; sub < 2; sub++) {
                        float* cc = acc[mt][2 * p + sub];
                        mma16816(cc, ah[mt], &bh[2 * sub]);
                        mma16816(cc, al[mt], &bh[2 * sub]);
                        mma16816(cc, ah[mt], &bl[2 * sub]);
                    }
            }
        }
        __syncthreads();
    }

    // epilogue: lane holds rows l/4, l/4+8 per m16 tile; cols 2*(l%4)+{0,1} per n8 tile
    const int rl = l >> 2;
    const int cl = (l & 3) * 2;
#pragma unroll
    for (int mt = 0; mt < 2; mt++) {
#pragma unroll
        for (int rh = 0; rh < 2; rh++) {
            int r = row0 + wm * 32 + mt * 16 + rh * 8 + rl;
#pragma unroll
            for (int nt = 0; nt < 8; nt++) {
                int cix = col0 + wn * 64 + nt * 8 + cl;
                float v0 = acc[mt][nt][rh * 2 + 0];
                float v1 = acc[mt][nt][rh * 2 + 1];
                if (bias) { v0 += bias[cix]; v1 += bias[cix + 1]; }
                if (C) {
                    float2 o = make_float2(v0, v1);
                    *(float2*)(C + (size_t)r * ldc + cix) = o;
                } else {
                    __nv_bfloat16 h0 = __float2bfloat16_rn(v0);
                    __nv_bfloat16 h1 = __float2bfloat16_rn(v1);
                    size_t ui = ((size_t)r * ldc + cix) >> 1;
                    __nv_bfloat162 hp; hp.x = h0; hp.y = h1;
                    ((uint32_t*)Ch)[ui] = *reinterpret_cast<uint32_t*>(&hp);
                    ((uint32_t*)Cl)[ui] = pack_bf2(v0 - __bfloat162float(h0),
                                                   v1 - __bfloat162float(h1));
                }
            }
        }
    }
}

// ---------------------------------------------------------------------------
// producers: normalize + split, weight transpose + split, pad zeroing
// ---------------------------------------------------------------------------
__global__ void norm_split(const float* __restrict__ emb,
                           __nv_bfloat16* __restrict__ Ah, __nv_bfloat16* __restrict__ Al) {
    int gw = (blockIdx.x * blockDim.x + threadIdx.x) >> 5;
    if (gw >= NODES) return;
    int lane = threadIdx.x & 31;
    float4 v = ((const float4*)(emb + (size_t)gw * EDIM))[lane];
    float ss = v.x * v.x + v.y * v.y + v.z * v.z + v.w * v.w;
#pragma unroll
    for (int o = 16; o > 0; o >>= 1) ss += __shfl_xor_sync(0xffffffffu, ss, o);
    float inv = 1.0f / fmaxf(sqrtf(ss), 1e-12f);
    v.x *= inv; v.y *= inv; v.z *= inv; v.w *= inv;
    __nv_bfloat16 hx = __float2bfloat16_rn(v.x), hy = __float2bfloat16_rn(v.y);
    __nv_bfloat16 hz = __float2bfloat16_rn(v.z), hw = __float2bfloat16_rn(v.w);
    size_t ui = ((size_t)gw * EDIM + lane * 4) >> 1;
    __nv_bfloat162 p0; p0.x = hx; p0.y = hy;
    __nv_bfloat162 p1; p1.x = hz; p1.y = hw;
    ((uint32_t*)Ah)[ui]     = *reinterpret_cast<uint32_t*>(&p0);
    ((uint32_t*)Ah)[ui + 1] = *reinterpret_cast<uint32_t*>(&p1);
    ((uint32_t*)Al)[ui]     = pack_bf2(v.x - __bfloat162float(hx), v.y - __bfloat162float(hy));
    ((uint32_t*)Al)[ui + 1] = pack_bf2(v.z - __bfloat162float(hz), v.w - __bfloat162float(hw));
}

__global__ void zero_pad(__nv_bfloat16* Ah, __nv_bfloat16* Al, int K) {
    int n = (MPAD - NODES) * K / 2;
    int i = blockIdx.x * blockDim.x + threadIdx.x;
    if (i < n) {
        ((uint32_t*)(Ah + (size_t)NODES * K))[i] = 0;
        ((uint32_t*)(Al + (size_t)NODES * K))[i] = 0;
    }
}

__global__ void split_bt_proj(const float* __restrict__ W) {   // [128,768] -> Bt [768,128]
    int idx = blockIdx.x * blockDim.x + threadIdx.x;
    if (idx >= EDIM * PDIM) return;
    int k = idx / PDIM, n = idx % PDIM;
    float v = W[idx];
    __nv_bfloat16 h = __float2bfloat16_rn(v);
    g_Bth[(size_t)n * EDIM + k] = h;
    g_Btl[(size_t)n * EDIM + k] = __float2bfloat16_rn(v - __bfloat162float(h));
}

__global__ void split_bt_layer(const float* __restrict__ bases, const float* __restrict__ root, int K) {
    int z = blockIdx.z;
    const float* in = (z < 2) ? bases + (size_t)z * K * HID : root;
    int idx = blockIdx.x * blockDim.x + threadIdx.x;
    if (idx >= K * HID) return;
    int k = idx / HID, n = idx % HID;
    float v = in[idx];
    __nv_bfloat16 h = __float2bfloat16_rn(v);
    size_t o = ((size_t)z * HID + n) * K + k;
    g_Bth[o] = h;
    g_Btl[o] = __float2bfloat16_rn(v - __bfloat162float(h));
}

// ---------------------------------------------------------------------------
// edge machinery + batchnorm
// ---------------------------------------------------------------------------
__global__ void zero_cnt() {
    int i = blockIdx.x * blockDim.x + threadIdx.x;
    if (i < NODES * NREL) g_cnt[i] = 0;
}
__global__ void count_edges(const int* __restrict__ dst, const int* __restrict__ et) {
    int e = blockIdx.x * blockDim.x + threadIdx.x;
    if (e < NEDGE) atomicAdd(&g_cnt[dst[e] * NREL + et[e]], 1);
}
__global__ void compute_invd(const int* __restrict__ dst, const int* __restrict__ et) {
    int e = blockIdx.x * blockDim.x + threadIdx.x;
    if (e < NEDGE) {
        int c = g_cnt[dst[e] * NREL + et[e]];
        g_invd[e] = 1.0f / (float)(c > 0 ? c : 1);
    }
}
__global__ void edge_agg(const int* __restrict__ src, const int* __restrict__ dst,
                         const int* __restrict__ et, const float* __restrict__ comp) {
    int gw = (blockIdx.x * blockDim.x + threadIdx.x) >> 5;
    if (gw >= NEDGE) return;
    int lane = threadIdx.x & 31;
    int s = src[gw], d = dst[gw], r = et[gw];
    float w = g_invd[gw];
    float c0 = comp[r * 2 + 0] * w;
    float c1 = comp[r * 2 + 1] * w;
    const float4* p0 = (const float4*)&g_h0[(size_t)s * HID];
    const float4* p1 = (const float4*)&g_h1[(size_t)s * HID];
    float* po = &g_buf[(size_t)d * HID];
#pragma unroll
    for (int i = 0; i < 2; i++) {
        int c = lane + i * 32;
        float4 a = p0[c], b = p1[c];
        atomicAdd(&po[c * 4 + 0], fmaf(c0, a.x, c1 * b.x));
        atomicAdd(&po[c * 4 + 1], fmaf(c0, a.y, c1 * b.y));
        atomicAdd(&po[c * 4 + 2], fmaf(c0, a.z, c1 * b.z));
        atomicAdd(&po[c * 4 + 3], fmaf(c0, a.w, c1 * b.w));
    }
}

__global__ void zero_stats() {
    int c = threadIdx.x;
    g_sum[c] = 0.f; g_sumsq[c] = 0.f;
}
__global__ void bn_stats() {
    int c = threadIdx.x;
    float s = 0.f, ss = 0.f;
    for (int r = blockIdx.x; r < NODES; r += gridDim.x) {
        float v = g_buf[(size_t)r * HID + c];
        s += v; ss += v * v;
    }
    atomicAdd(&g_sum[c], s);
    atomicAdd(&g_sumsq[c], ss);
}
__global__ void bn_finalize(const float* __restrict__ gamma, const float* __restrict__ beta) {
    int c = threadIdx.x;
    const float invM = 1.0f / (float)NODES;
    float mean = g_sum[c] * invM;
    float var = g_sumsq[c] * invM - mean * mean;
    float sc = gamma[c] * rsqrtf(var + BN_EPS);
    g_scale[c] = sc;
    g_shift[c] = beta[c] - mean * sc;
}
__global__ void bn_apply_f32(float* __restrict__ out) {
    int idx = blockIdx.x * blockDim.x + threadIdx.x;
    if (idx >= NODES * HID / 4) return;
    int c4 = (idx & 63) << 2;
    float4 v = ((const float4*)g_buf)[idx];
    float4 sc = *(const float4*)&g_scale[c4];
    float4 sh = *(const float4*)&g_shift[c4];
    v.x = fmaxf(fmaf(v.x, sc.x, sh.x), 0.f);
    v.y = fmaxf(fmaf(v.y, sc.y, sh.y), 0.f);
    v.z = fmaxf(fmaf(v.z, sc.z, sh.z), 0.f);
    v.w = fmaxf(fmaf(v.w, sc.w, sh.w), 0.f);
    ((float4*)out)[idx] = v;
}
__global__ void bn_apply_split(__nv_bfloat16* __restrict__ Ah, __nv_bfloat16* __restrict__ Al) {
    int idx = blockIdx.x * blockDim.x + threadIdx.x;
    if (idx >= NODES * HID / 4) return;
    int c4 = (idx & 63) << 2;
    float4 v = ((const float4*)g_buf)[idx];
    float4 sc = *(const float4*)&g_scale[c4];
    float4 sh = *(const float4*)&g_shift[c4];
    v.x = fmaxf(fmaf(v.x, sc.x, sh.x), 0.f);
    v.y = fmaxf(fmaf(v.y, sc.y, sh.y), 0.f);
    v.z = fmaxf(fmaf(v.z, sc.z, sh.z), 0.f);
    v.w = fmaxf(fmaf(v.w, sc.w, sh.w), 0.f);
    __nv_bfloat16 hx = __float2bfloat16_rn(v.x), hy = __float2bfloat16_rn(v.y);
    __nv_bfloat16 hz = __float2bfloat16_rn(v.z), hw = __float2bfloat16_rn(v.w);
    __nv_bfloat162 p0; p0.x = hx; p0.y = hy;
    __nv_bfloat162 p1; p1.x = hz; p1.y = hw;
    ((uint32_t*)Ah)[idx * 2]     = *reinterpret_cast<uint32_t*>(&p0);
    ((uint32_t*)Ah)[idx * 2 + 1] = *reinterpret_cast<uint32_t*>(&p1);
    ((uint32_t*)Al)[idx * 2]     = pack_bf2(v.x - __bfloat162float(hx), v.y - __bfloat162float(hy));
    ((uint32_t*)Al)[idx * 2 + 1] = pack_bf2(v.z - __bfloat162float(hz), v.w - __bfloat162float(hw));
}

// ---------------------------------------------------------------------------
// host launch
// ---------------------------------------------------------------------------
extern "C" void kernel_launch(void* const* d_in, const int* in_sizes, int n_in,
                              void* d_out, int out_size) {
    const int* edge_index = (const int*)d_in[0];
    const int* src = edge_index;
    const int* dst = edge_index + NEDGE;
    const int* etype = (const int*)d_in[1];
    const float* emb = (const float*)d_in[2];
    const float* proj_w = (const float*)d_in[3];
    const float* proj_b = (const float*)d_in[4];

    const float *comp[3], *bases[3], *root[3], *bias[3], *gamma[3], *beta[3];
    for (int l = 0; l < 3; l++) {
        comp[l]  = (const float*)d_in[5 + 6 * l];
        bases[l] = (const float*)d_in[6 + 6 * l];
        root[l]  = (const float*)d_in[7 + 6 * l];
        bias[l]  = (const float*)d_in[8 + 6 * l];
        gamma[l] = (const float*)d_in[9 + 6 * l];
        beta[l]  = (const float*)d_in[10 + 6 * l];
    }

    __nv_bfloat16 *Ah0, *Al0, *Ah1, *Al1, *Bth, *Btl;
    float *h0, *h1, *buf;
    cudaGetSymbolAddress((void**)&Ah0, g_Ah0);
    cudaGetSymbolAddress((void**)&Al0, g_Al0);
    cudaGetSymbolAddress((void**)&Ah1, g_Ah1);
    cudaGetSymbolAddress((void**)&Al1, g_Al1);
    cudaGetSymbolAddress((void**)&Bth, g_Bth);
    cudaGetSymbolAddress((void**)&Btl, g_Btl);
    cudaGetSymbolAddress((void**)&h0, g_h0);
    cudaGetSymbolAddress((void**)&h1, g_h1);
    cudaGetSymbolAddress((void**)&buf, g_buf);

    cudaFuncSetAttribute(gemm_mma, cudaFuncAttributeMaxDynamicSharedMemorySize, SMEM_GEMM);

    // normalize + split -> set0 (K=128)
    norm_split<<<(NODES * 32 + 255) / 256, 256>>>(emb, Ah0, Al0);
    zero_pad<<<(48 * EDIM / 2 + 255) / 256, 256>>>(Ah0, Al0, EDIM);
    split_bt_proj<<<(EDIM * PDIM + 255) / 256, 256>>>(proj_w);
    zero_cnt<<<(NODES * NREL + 255) / 256, 256>>>();
    count_edges<<<(NEDGE + 255) / 256, 256>>>(dst, etype);

    // proj GEMM -> split output into set1 (K=768 for next layer), bias fused
    {
        dim3 grid(MBLK, 6, 1);    // nbz = 6
        gemm_mma<<<grid, 256, SMEM_GEMM>>>(
            Ah0, Al0, EDIM, 6, Bth, Btl,
            nullptr, nullptr, nullptr, PDIM,
            proj_b, proj_b, proj_b,
            Ah1, Al1);
    }
    compute_invd<<<(NEDGE + 255) / 256, 256>>>(dst, etype);

    for (int l = 0; l < 3; l++) {
        int K = (l == 0) ? PDIM : HID;
        __nv_bfloat16* Ah = (l == 1) ? Ah0 : Ah1;   // l0:set1, l1:set0, l2:set1
        __nv_bfloat16* Al = (l == 1) ? Al0 : Al1;

        zero_pad<<<(48 * K / 2 + 255) / 256, 256>>>(Ah, Al, K);
        {
            dim3 g((K * HID + 255) / 256, 1, 3);
            split_bt_layer<<<g, 256>>>(bases[l], root[l], K);
        }
        {
            dim3 grid(MBLK, 2, 3);    // nbz = 2 (N=256 per matrix)
            gemm_mma<<<grid, 256, SMEM_GEMM>>>(
                Ah, Al, K, 2, Bth, Btl,
                h0, h1, buf, HID,
                nullptr, nullptr, bias[l],
                nullptr, nullptr);
        }
        edge_agg<<<NEDGE / 8, 256>>>(src, dst, etype, comp[l]);

        zero_stats<<<1, HID>>>();
        bn_stats<<<256, HID>>>();
        bn_finalize<<<1, HID>>>(gamma[l], beta[l]);
        if (l < 2) {
            __nv_bfloat16* oAh = (l == 0) ? Ah0 : Ah1;
            __nv_bfloat16* oAl = (l == 0) ? Al0 : Al1;
            bn_apply_split<<<(NODES * HID / 4 + 255) / 256, 256>>>(oAh, oAl);
        } else {
            bn_apply_f32<<<(NODES * HID / 4 + 255) / 256, 256>>>((float*)d_out);
        }
    }
}

// round 4
// speedup vs baseline: 1.6293x; 1.0372x over previous
#include <cuda_runtime.h>
#include <cuda_bf16.h>
#include <cstdint>

#define NODES 50000
#define MPAD  50176          // 196 * 256
#define EDIM  128
#define PDIM  768
#define HID   256
#define NREL  16
#define NEDGE 400000
#define BN_EPS 1e-5f
#define MBLK  196            // MPAD / 256

// ---------------------------------------------------------------------------
// scratch (static device memory; no allocations)
// ---------------------------------------------------------------------------
__device__ __nv_bfloat16 g_Ah0[(size_t)MPAD * PDIM];
__device__ __nv_bfloat16 g_Al0[(size_t)MPAD * PDIM];
__device__ __nv_bfloat16 g_Ah1[(size_t)MPAD * PDIM];
__device__ __nv_bfloat16 g_Al1[(size_t)MPAD * PDIM];
__device__ __nv_bfloat16 g_Bth[3 * 256 * 768];          // split-B^T (K-major, [N,K])
__device__ __nv_bfloat16 g_Btl[3 * 256 * 768];
__device__ float g_h0[(size_t)MPAD * HID];
__device__ float g_h1[(size_t)MPAD * HID];
__device__ float g_buf[(size_t)MPAD * HID];
__device__ int   g_cnt[NODES * NREL];
__device__ float g_invd[NEDGE];
__device__ float g_sum[HID], g_sumsq[HID], g_scale[HID], g_shift[HID];

// ---------------------------------------------------------------------------
// helpers
// ---------------------------------------------------------------------------
__device__ __forceinline__ uint32_t smem_u32(const void* p) {
    uint32_t a;
    asm("{ .reg .u64 t; cvta.to.shared.u64 t, %1; cvt.u32.u64 %0, t; }" : "=r"(a) : "l"(p));
    return a;
}
__device__ __forceinline__ void cp16(uint32_t dst, const void* src) {
    asm volatile("cp.async.cg.shared.global [%0], [%1], 16;" :: "r"(dst), "l"(src) : "memory");
}
__device__ __forceinline__ void ldsm4(uint32_t* r, uint32_t addr) {
    asm volatile("ldmatrix.sync.aligned.m8n8.x4.shared.b16 {%0,%1,%2,%3}, [%4];"
                 : "=r"(r[0]), "=r"(r[1]), "=r"(r[2]), "=r"(r[3]) : "r"(addr));
}
__device__ __forceinline__ void mma16816(float* c, const uint32_t* a, const uint32_t* b) {
    asm volatile("mma.sync.aligned.m16n8k16.row.col.f32.bf16.bf16.f32 "
                 "{%0,%1,%2,%3}, {%4,%5,%6,%7}, {%8,%9}, {%0,%1,%2,%3};"
                 : "+f"(c[0]), "+f"(c[1]), "+f"(c[2]), "+f"(c[3])
                 : "r"(a[0]), "r"(a[1]), "r"(a[2]), "r"(a[3]), "r"(b[0]), "r"(b[1]));
}
static __device__ __forceinline__ uint32_t pack_bf2(float a, float b) {
    __nv_bfloat162 t;
    t.x = __float2bfloat16_rn(a);
    t.y = __float2bfloat16_rn(b);
    return *reinterpret_cast<uint32_t*>(&t);
}

// smem per stage: Ah(256x144) | Al | Bh(128x144) | Bl
#define ROWB    144
#define A_MAT   36864          // 256*144
#define B_MAT   18432          // 128*144
#define B_BASE  73728          // 2*A_MAT
#define STAGEB  110592         // 2*A_MAT + 2*B_MAT
#define SMEM_GEMM (2 * STAGEB) // 221184

// ---------------------------------------------------------------------------
// split-bf16 GEMM via mma.sync: C = A @ B^T (+bias)
// CTA tile 256x128, 512 threads, warp tile 64x32, K-chunk 64, 2-stage cp.async
// ---------------------------------------------------------------------------
__device__ __forceinline__ void load_stage(
    uint32_t sb, int stage, int k0,
    const __nv_bfloat16* __restrict__ Ah, const __nv_bfloat16* __restrict__ Al,
    const __nv_bfloat16* __restrict__ Bh, const __nv_bfloat16* __restrict__ Bl,
    int K, int t)
{
    uint32_t base = sb + stage * STAGEB;
    // A tiles: 256 rows x 8 16B-units each, for h and l
#pragma unroll
    for (int i = 0; i < 4; i++) {
        int unit = t + i * 512;
        int r = unit >> 3, u = unit & 7;
        uint32_t off = r * ROWB + u * 16;
        cp16(base + off,         Ah + (size_t)r * K + k0 + u * 8);
        cp16(base + A_MAT + off, Al + (size_t)r * K + k0 + u * 8);
    }
    // B tiles: 128 rows x 8 units
#pragma unroll
    for (int i = 0; i < 2; i++) {
        int unit = t + i * 512;
        int r = unit >> 3, u = unit & 7;
        uint32_t off = r * ROWB + u * 16;
        cp16(base + B_BASE + off,         Bh + (size_t)r * K + k0 + u * 8);
        cp16(base + B_BASE + B_MAT + off, Bl + (size_t)r * K + k0 + u * 8);
    }
    asm volatile("cp.async.commit_group;" ::: "memory");
}

__global__ void __launch_bounds__(512, 1) gemm_mma(
    const __nv_bfloat16* __restrict__ Ah, const __nv_bfloat16* __restrict__ Al,
    int K, int nbz,
    const __nv_bfloat16* __restrict__ Bth, const __nv_bfloat16* __restrict__ Btl,
    float* C0, float* C1, float* C2, int ldc,
    const float* bias0, const float* bias1, const float* bias2,
    __nv_bfloat16* Ch, __nv_bfloat16* Cl)
{
    extern __shared__ char smem[];
    uint32_t sb = smem_u32(smem);
    const int t = threadIdx.x;
    const int w = t >> 5, l = t & 31;
    const int wm = w >> 2, wn = w & 3;
    const int row0 = blockIdx.x * 256;
    const int col0 = blockIdx.y * 128;
    const int z = blockIdx.z;

    float* C = (z == 0) ? C0 : (z == 1) ? C1 : C2;
    const float* bias = (z == 0) ? bias0 : (z == 1) ? bias1 : bias2;

    const __nv_bfloat16* A_h = Ah + (size_t)row0 * K;
    const __nv_bfloat16* A_l = Al + (size_t)row0 * K;
    size_t Boff = (size_t)(z * nbz + blockIdx.y) * 128 * K;
    const __nv_bfloat16* B_h = Bth + Boff;
    const __nv_bfloat16* B_l = Btl + Boff;

    // ldmatrix per-lane offsets
    const uint32_t aoff = (uint32_t)((wm * 64 + (l & 15)) * ROWB + (l >> 4) * 16);
    const uint32_t boff = (uint32_t)((wn * 32 + (l & 7) + ((l >> 4) & 1) * 8) * ROWB
                                     + ((l >> 3) & 1) * 16);

    float acc[4][4][4];
#pragma unroll
    for (int mt = 0; mt < 4; mt++)
#pragma unroll
        for (int nt = 0; nt < 4; nt++)
#pragma unroll
            for (int j = 0; j < 4; j++) acc[mt][nt][j] = 0.f;

    const int nch = K >> 6;
    load_stage(sb, 0, 0, A_h, A_l, B_h, B_l, K, t);

    for (int c = 0; c < nch; c++) {
        if (c + 1 < nch) {
            load_stage(sb, (c + 1) & 1, (c + 1) << 6, A_h, A_l, B_h, B_l, K, t);
            asm volatile("cp.async.wait_group 1;" ::: "memory");
        } else {
            asm volatile("cp.async.wait_group 0;" ::: "memory");
        }
        __syncthreads();

        uint32_t Abase = sb + (c & 1) * STAGEB;
        uint32_t Bbase = Abase + B_BASE;
#pragma unroll
        for (int ks = 0; ks < 4; ks++) {
            uint32_t bh[2][4], bl[2][4];
#pragma unroll
            for (int p = 0; p < 2; p++) {
                ldsm4(bh[p], Bbase + boff + p * 2304 + ks * 32);
                ldsm4(bl[p], Bbase + B_MAT + boff + p * 2304 + ks * 32);
            }
#pragma unroll
            for (int mt = 0; mt < 4; mt++) {
                uint32_t ah[4], al[4];
                ldsm4(ah, Abase + aoff + mt * 2304 + ks * 32);
                ldsm4(al, Abase + A_MAT + aoff + mt * 2304 + ks * 32);
#pragma unroll
                for (int nt = 0; nt < 4; nt++) {
                    float* cc = acc[mt][nt];
                    const uint32_t* bph = &bh[nt >> 1][(nt & 1) * 2];
                    const uint32_t* bpl = &bl[nt >> 1][(nt & 1) * 2];
                    mma16816(cc, ah, bph);
                    mma16816(cc, al, bph);
                    mma16816(cc, ah, bpl);
                }
            }
        }
        __syncthreads();
    }

    // epilogue
    const int rl = l >> 2;
    const int cl = (l & 3) * 2;
#pragma unroll
    for (int mt = 0; mt < 4; mt++) {
#pragma unroll
        for (int rh = 0; rh < 2; rh++) {
            int r = row0 + wm * 64 + mt * 16 + rh * 8 + rl;
#pragma unroll
            for (int nt = 0; nt < 4; nt++) {
                int cix = col0 + wn * 32 + nt * 8 + cl;
                float v0 = acc[mt][nt][rh * 2 + 0];
                float v1 = acc[mt][nt][rh * 2 + 1];
                if (bias) { v0 += bias[cix]; v1 += bias[cix + 1]; }
                if (C) {
                    *(float2*)(C + (size_t)r * ldc + cix) = make_float2(v0, v1);
                } else {
                    __nv_bfloat16 h0 = __float2bfloat16_rn(v0);
                    __nv_bfloat16 h1 = __float2bfloat16_rn(v1);
                    size_t ui = ((size_t)r * ldc + cix) >> 1;
                    __nv_bfloat162 hp; hp.x = h0; hp.y = h1;
                    ((uint32_t*)Ch)[ui] = *reinterpret_cast<uint32_t*>(&hp);
                    ((uint32_t*)Cl)[ui] = pack_bf2(v0 - __bfloat162float(h0),
                                                   v1 - __bfloat162float(h1));
                }
            }
        }
    }
}

// ---------------------------------------------------------------------------
// producers
// ---------------------------------------------------------------------------
__global__ void norm_split(const float* __restrict__ emb,
                           __nv_bfloat16* __restrict__ Ah, __nv_bfloat16* __restrict__ Al) {
    int gw = (blockIdx.x * blockDim.x + threadIdx.x) >> 5;
    if (gw >= NODES) return;
    int lane = threadIdx.x & 31;
    float4 v = ((const float4*)(emb + (size_t)gw * EDIM))[lane];
    float ss = v.x * v.x + v.y * v.y + v.z * v.z + v.w * v.w;
#pragma unroll
    for (int o = 16; o > 0; o >>= 1) ss += __shfl_xor_sync(0xffffffffu, ss, o);
    float inv = 1.0f / fmaxf(sqrtf(ss), 1e-12f);
    v.x *= inv; v.y *= inv; v.z *= inv; v.w *= inv;
    __nv_bfloat16 hx = __float2bfloat16_rn(v.x), hy = __float2bfloat16_rn(v.y);
    __nv_bfloat16 hz = __float2bfloat16_rn(v.z), hw = __float2bfloat16_rn(v.w);
    size_t ui = ((size_t)gw * EDIM + lane * 4) >> 1;
    __nv_bfloat162 p0; p0.x = hx; p0.y = hy;
    __nv_bfloat162 p1; p1.x = hz; p1.y = hw;
    ((uint32_t*)Ah)[ui]     = *reinterpret_cast<uint32_t*>(&p0);
    ((uint32_t*)Ah)[ui + 1] = *reinterpret_cast<uint32_t*>(&p1);
    ((uint32_t*)Al)[ui]     = pack_bf2(v.x - __bfloat162float(hx), v.y - __bfloat162float(hy));
    ((uint32_t*)Al)[ui + 1] = pack_bf2(v.z - __bfloat162float(hz), v.w - __bfloat162float(hw));
}

__global__ void zero_pad(__nv_bfloat16* Ah, __nv_bfloat16* Al, int K) {
    int n = (MPAD - NODES) * K / 2;
    int i = blockIdx.x * blockDim.x + threadIdx.x;
    if (i < n) {
        ((uint32_t*)(Ah + (size_t)NODES * K))[i] = 0;
        ((uint32_t*)(Al + (size_t)NODES * K))[i] = 0;
    }
}

__global__ void split_bt_proj(const float* __restrict__ W) {   // [128,768] -> Bt [768,128]
    int idx = blockIdx.x * blockDim.x + threadIdx.x;
    if (idx >= EDIM * PDIM) return;
    int k = idx / PDIM, n = idx % PDIM;
    float v = W[idx];
    __nv_bfloat16 h = __float2bfloat16_rn(v);
    g_Bth[(size_t)n * EDIM + k] = h;
    g_Btl[(size_t)n * EDIM + k] = __float2bfloat16_rn(v - __bfloat162float(h));
}

__global__ void split_bt_layer(const float* __restrict__ bases, const float* __restrict__ root, int K) {
    int z = blockIdx.z;
    const float* in = (z < 2) ? bases + (size_t)z * K * HID : root;
    int idx = blockIdx.x * blockDim.x + threadIdx.x;
    if (idx >= K * HID) return;
    int k = idx / HID, n = idx % HID;
    float v = in[idx];
    __nv_bfloat16 h = __float2bfloat16_rn(v);
    size_t o = ((size_t)z * HID + n) * K + k;
    g_Bth[o] = h;
    g_Btl[o] = __float2bfloat16_rn(v - __bfloat162float(h));
}

// ---------------------------------------------------------------------------
// edge machinery + batchnorm
// ---------------------------------------------------------------------------
__global__ void zero_cnt() {
    int i = blockIdx.x * blockDim.x + threadIdx.x;
    if (i < NODES * NREL) g_cnt[i] = 0;
}
__global__ void count_edges(const int* __restrict__ dst, const int* __restrict__ et) {
    int e = blockIdx.x * blockDim.x + threadIdx.x;
    if (e < NEDGE) atomicAdd(&g_cnt[dst[e] * NREL + et[e]], 1);
}
__global__ void compute_invd(const int* __restrict__ dst, const int* __restrict__ et) {
    int e = blockIdx.x * blockDim.x + threadIdx.x;
    if (e < NEDGE) {
        int c = g_cnt[dst[e] * NREL + et[e]];
        g_invd[e] = 1.0f / (float)(c > 0 ? c : 1);
    }
}
__global__ void edge_agg(const int* __restrict__ src, const int* __restrict__ dst,
                         const int* __restrict__ et, const float* __restrict__ comp) {
    int gw = (blockIdx.x * blockDim.x + threadIdx.x) >> 5;
    if (gw >= NEDGE) return;
    int lane = threadIdx.x & 31;
    int s = src[gw], d = dst[gw], r = et[gw];
    float w = g_invd[gw];
    float c0 = comp[r * 2 + 0] * w;
    float c1 = comp[r * 2 + 1] * w;
    const float4* p0 = (const float4*)&g_h0[(size_t)s * HID];
    const float4* p1 = (const float4*)&g_h1[(size_t)s * HID];
    float* po = &g_buf[(size_t)d * HID];
#pragma unroll
    for (int i = 0; i < 2; i++) {
        int c = lane + i * 32;
        float4 a = p0[c], b = p1[c];
        atomicAdd(&po[c * 4 + 0], fmaf(c0, a.x, c1 * b.x));
        atomicAdd(&po[c * 4 + 1], fmaf(c0, a.y, c1 * b.y));
        atomicAdd(&po[c * 4 + 2], fmaf(c0, a.z, c1 * b.z));
        atomicAdd(&po[c * 4 + 3], fmaf(c0, a.w, c1 * b.w));
    }
}

__global__ void zero_stats() {
    int c = threadIdx.x;
    g_sum[c] = 0.f; g_sumsq[c] = 0.f;
}
__global__ void bn_stats() {
    int c = threadIdx.x;
    float s = 0.f, ss = 0.f;
    for (int r = blockIdx.x; r < NODES; r += gridDim.x) {
        float v = g_buf[(size_t)r * HID + c];
        s += v; ss += v * v;
    }
    atomicAdd(&g_sum[c], s);
    atomicAdd(&g_sumsq[c], ss);
}
__global__ void bn_finalize(const float* __restrict__ gamma, const float* __restrict__ beta) {
    int c = threadIdx.x;
    const float invM = 1.0f / (float)NODES;
    float mean = g_sum[c] * invM;
    float var = g_sumsq[c] * invM - mean * mean;
    float sc = gamma[c] * rsqrtf(var + BN_EPS);
    g_scale[c] = sc;
    g_shift[c] = beta[c] - mean * sc;
}
__global__ void bn_apply_f32(float* __restrict__ out) {
    int idx = blockIdx.x * blockDim.x + threadIdx.x;
    if (idx >= NODES * HID / 4) return;
    int c4 = (idx & 63) << 2;
    float4 v = ((const float4*)g_buf)[idx];
    float4 sc = *(const float4*)&g_scale[c4];
    float4 sh = *(const float4*)&g_shift[c4];
    v.x = fmaxf(fmaf(v.x, sc.x, sh.x), 0.f);
    v.y = fmaxf(fmaf(v.y, sc.y, sh.y), 0.f);
    v.z = fmaxf(fmaf(v.z, sc.z, sh.z), 0.f);
    v.w = fmaxf(fmaf(v.w, sc.w, sh.w), 0.f);
    ((float4*)out)[idx] = v;
}
__global__ void bn_apply_split(__nv_bfloat16* __restrict__ Ah, __nv_bfloat16* __restrict__ Al) {
    int idx = blockIdx.x * blockDim.x + threadIdx.x;
    if (idx >= NODES * HID / 4) return;
    int c4 = (idx & 63) << 2;
    float4 v = ((const float4*)g_buf)[idx];
    float4 sc = *(const float4*)&g_scale[c4];
    float4 sh = *(const float4*)&g_shift[c4];
    v.x = fmaxf(fmaf(v.x, sc.x, sh.x), 0.f);
    v.y = fmaxf(fmaf(v.y, sc.y, sh.y), 0.f);
    v.z = fmaxf(fmaf(v.z, sc.z, sh.z), 0.f);
    v.w = fmaxf(fmaf(v.w, sc.w, sh.w), 0.f);
    __nv_bfloat16 hx = __float2bfloat16_rn(v.x), hy = __float2bfloat16_rn(v.y);
    __nv_bfloat16 hz = __float2bfloat16_rn(v.z), hw = __float2bfloat16_rn(v.w);
    __nv_bfloat162 p0; p0.x = hx; p0.y = hy;
    __nv_bfloat162 p1; p1.x = hz; p1.y = hw;
    ((uint32_t*)Ah)[idx * 2]     = *reinterpret_cast<uint32_t*>(&p0);
    ((uint32_t*)Ah)[idx * 2 + 1] = *reinterpret_cast<uint32_t*>(&p1);
    ((uint32_t*)Al)[idx * 2]     = pack_bf2(v.x - __bfloat162float(hx), v.y - __bfloat162float(hy));
    ((uint32_t*)Al)[idx * 2 + 1] = pack_bf2(v.z - __bfloat162float(hz), v.w - __bfloat162float(hw));
}

// ---------------------------------------------------------------------------
// host launch
// ---------------------------------------------------------------------------
extern "C" void kernel_launch(void* const* d_in, const int* in_sizes, int n_in,
                              void* d_out, int out_size) {
    const int* edge_index = (const int*)d_in[0];
    const int* src = edge_index;
    const int* dst = edge_index + NEDGE;
    const int* etype = (const int*)d_in[1];
    const float* emb = (const float*)d_in[2];
    const float* proj_w = (const float*)d_in[3];
    const float* proj_b = (const float*)d_in[4];

    const float *comp[3], *bases[3], *root[3], *bias[3], *gamma[3], *beta[3];
    for (int l = 0; l < 3; l++) {
        comp[l]  = (const float*)d_in[5 + 6 * l];
        bases[l] = (const float*)d_in[6 + 6 * l];
        root[l]  = (const float*)d_in[7 + 6 * l];
        bias[l]  = (const float*)d_in[8 + 6 * l];
        gamma[l] = (const float*)d_in[9 + 6 * l];
        beta[l]  = (const float*)d_in[10 + 6 * l];
    }

    __nv_bfloat16 *Ah0, *Al0, *Ah1, *Al1, *Bth, *Btl;
    float *h0, *h1, *buf;
    cudaGetSymbolAddress((void**)&Ah0, g_Ah0);
    cudaGetSymbolAddress((void**)&Al0, g_Al0);
    cudaGetSymbolAddress((void**)&Ah1, g_Ah1);
    cudaGetSymbolAddress((void**)&Al1, g_Al1);
    cudaGetSymbolAddress((void**)&Bth, g_Bth);
    cudaGetSymbolAddress((void**)&Btl, g_Btl);
    cudaGetSymbolAddress((void**)&h0, g_h0);
    cudaGetSymbolAddress((void**)&h1, g_h1);
    cudaGetSymbolAddress((void**)&buf, g_buf);

    cudaFuncSetAttribute(gemm_mma, cudaFuncAttributeMaxDynamicSharedMemorySize, SMEM_GEMM);

    // normalize + split -> set0 (K=128)
    norm_split<<<(NODES * 32 + 255) / 256, 256>>>(emb, Ah0, Al0);
    zero_pad<<<((MPAD - NODES) * EDIM / 2 + 255) / 256, 256>>>(Ah0, Al0, EDIM);
    split_bt_proj<<<(EDIM * PDIM + 255) / 256, 256>>>(proj_w);
    zero_cnt<<<(NODES * NREL + 255) / 256, 256>>>();
    count_edges<<<(NEDGE + 255) / 256, 256>>>(dst, etype);

    // proj GEMM -> split output into set1 (K=768 for next layer), bias fused
    {
        dim3 grid(MBLK, 6, 1);    // nbz = 6
        gemm_mma<<<grid, 512, SMEM_GEMM>>>(
            Ah0, Al0, EDIM, 6, Bth, Btl,
            nullptr, nullptr, nullptr, PDIM,
            proj_b, proj_b, proj_b,
            Ah1, Al1);
    }
    compute_invd<<<(NEDGE + 255) / 256, 256>>>(dst, etype);

    for (int l = 0; l < 3; l++) {
        int K = (l == 0) ? PDIM : HID;
        __nv_bfloat16* Ah = (l == 1) ? Ah0 : Ah1;   // l0:set1, l1:set0, l2:set1
        __nv_bfloat16* Al = (l == 1) ? Al0 : Al1;

        zero_pad<<<((MPAD - NODES) * K / 2 + 255) / 256, 256>>>(Ah, Al, K);
        {
            dim3 g((K * HID + 255) / 256, 1, 3);
            split_bt_layer<<<g, 256>>>(bases[l], root[l], K);
        }
        {
            dim3 grid(MBLK, 2, 3);    // nbz = 2 (N=256 per matrix)
            gemm_mma<<<grid, 512, SMEM_GEMM>>>(
                Ah, Al, K, 2, Bth, Btl,
                h0, h1, buf, HID,
                nullptr, nullptr, bias[l],
                nullptr, nullptr);
        }
        edge_agg<<<NEDGE / 8, 256>>>(src, dst, etype, comp[l]);

        zero_stats<<<1, HID>>>();
        bn_stats<<<256, HID>>>();
        bn_finalize<<<1, HID>>>(gamma[l], beta[l]);
        if (l < 2) {
            __nv_bfloat16* oAh = (l == 0) ? Ah0 : Ah1;
            __nv_bfloat16* oAl = (l == 0) ? Al0 : Al1;
            bn_apply_split<<<(NODES * HID / 4 + 255) / 256, 256>>>(oAh, oAl);
        } else {
            bn_apply_f32<<<(NODES * HID / 4 + 255) / 256, 256>>>((float*)d_out);
        }
    }
}

// round 5
// speedup vs baseline: 2.1095x; 1.2948x over previous
#include <cuda_runtime.h>
#include <cuda_bf16.h>
#include <cstdint>

#define NODES 50000
#define MPAD  50176          // 196 * 256
#define EDIM  128
#define PDIM  768
#define HID   256
#define NREL  16
#define NEDGE 400000
#define BN_EPS 1e-5f
#define MBLK  196            // MPAD / 256
#define SCANB 196            // ceil(50000/256)

// ---------------------------------------------------------------------------
// scratch (static device memory; no allocations)
// ---------------------------------------------------------------------------
__device__ __nv_bfloat16 g_Ah0[(size_t)MPAD * PDIM];
__device__ __nv_bfloat16 g_Al0[(size_t)MPAD * PDIM];
__device__ __nv_bfloat16 g_Ah1[(size_t)MPAD * PDIM];
__device__ __nv_bfloat16 g_Al1[(size_t)MPAD * PDIM];
__device__ __nv_bfloat16 g_Bth[3 * 256 * 768];          // split-B^T (K-major, [N,K])
__device__ __nv_bfloat16 g_Btl[3 * 256 * 768];
__device__ float g_h0[(size_t)MPAD * HID];
__device__ float g_h1[(size_t)MPAD * HID];
__device__ float g_buf[(size_t)MPAD * HID];
__device__ int   g_cnt[NODES * NREL];     // per-(dst,rel) counts
__device__ int   g_cntnode[NODES];        // per-dst counts
__device__ int   g_fill[NODES];
__device__ int   g_rowptr[NODES + 1];
__device__ int   g_blksum[SCANB];
__device__ int   g_packed[NEDGE];         // src | (rel<<24), sorted by dst
__device__ float g_invw[NEDGE];           // 1/cnt(dst,rel), sorted by dst
__device__ float g_sum[HID], g_sumsq[HID], g_scale[HID], g_shift[HID];

// ---------------------------------------------------------------------------
// helpers
// ---------------------------------------------------------------------------
__device__ __forceinline__ uint32_t smem_u32(const void* p) {
    uint32_t a;
    asm("{ .reg .u64 t; cvta.to.shared.u64 t, %1; cvt.u32.u64 %0, t; }" : "=r"(a) : "l"(p));
    return a;
}
__device__ __forceinline__ void cp16(uint32_t dst, const void* src) {
    asm volatile("cp.async.cg.shared.global [%0], [%1], 16;" :: "r"(dst), "l"(src) : "memory");
}
__device__ __forceinline__ void ldsm4(uint32_t* r, uint32_t addr) {
    asm volatile("ldmatrix.sync.aligned.m8n8.x4.shared.b16 {%0,%1,%2,%3}, [%4];"
                 : "=r"(r[0]), "=r"(r[1]), "=r"(r[2]), "=r"(r[3]) : "r"(addr));
}
__device__ __forceinline__ void mma16816(float* c, const uint32_t* a, const uint32_t* b) {
    asm volatile("mma.sync.aligned.m16n8k16.row.col.f32.bf16.bf16.f32 "
                 "{%0,%1,%2,%3}, {%4,%5,%6,%7}, {%8,%9}, {%0,%1,%2,%3};"
                 : "+f"(c[0]), "+f"(c[1]), "+f"(c[2]), "+f"(c[3])
                 : "r"(a[0]), "r"(a[1]), "r"(a[2]), "r"(a[3]), "r"(b[0]), "r"(b[1]));
}
static __device__ __forceinline__ uint32_t pack_bf2(float a, float b) {
    __nv_bfloat162 t;
    t.x = __float2bfloat16_rn(a);
    t.y = __float2bfloat16_rn(b);
    return *reinterpret_cast<uint32_t*>(&t);
}

// smem per stage: Ah(256x144) | Al | Bh(128x144) | Bl
#define ROWB    144
#define A_MAT   36864
#define B_MAT   18432
#define B_BASE  73728
#define STAGEB  110592
#define SMEM_GEMM (2 * STAGEB)

// ---------------------------------------------------------------------------
// split-bf16 GEMM via mma.sync: C = A @ B^T (+bias)
// CTA tile 256x128, 512 threads, warp tile 64x32, K-chunk 64, 2-stage cp.async
// ---------------------------------------------------------------------------
__device__ __forceinline__ void load_stage(
    uint32_t sb, int stage, int k0,
    const __nv_bfloat16* __restrict__ Ah, const __nv_bfloat16* __restrict__ Al,
    const __nv_bfloat16* __restrict__ Bh, const __nv_bfloat16* __restrict__ Bl,
    int K, int t)
{
    uint32_t base = sb + stage * STAGEB;
#pragma unroll
    for (int i = 0; i < 4; i++) {
        int unit = t + i * 512;
        int r = unit >> 3, u = unit & 7;
        uint32_t off = r * ROWB + u * 16;
        cp16(base + off,         Ah + (size_t)r * K + k0 + u * 8);
        cp16(base + A_MAT + off, Al + (size_t)r * K + k0 + u * 8);
    }
#pragma unroll
    for (int i = 0; i < 2; i++) {
        int unit = t + i * 512;
        int r = unit >> 3, u = unit & 7;
        uint32_t off = r * ROWB + u * 16;
        cp16(base + B_BASE + off,         Bh + (size_t)r * K + k0 + u * 8);
        cp16(base + B_BASE + B_MAT + off, Bl + (size_t)r * K + k0 + u * 8);
    }
    asm volatile("cp.async.commit_group;" ::: "memory");
}

__global__ void __launch_bounds__(512, 1) gemm_mma(
    const __nv_bfloat16* __restrict__ Ah, const __nv_bfloat16* __restrict__ Al,
    int K, int nbz,
    const __nv_bfloat16* __restrict__ Bth, const __nv_bfloat16* __restrict__ Btl,
    float* C0, float* C1, float* C2, int ldc,
    const float* bias0, const float* bias1, const float* bias2,
    __nv_bfloat16* Ch, __nv_bfloat16* Cl)
{
    extern __shared__ char smem[];
    uint32_t sb = smem_u32(smem);
    const int t = threadIdx.x;
    const int w = t >> 5, l = t & 31;
    const int wm = w >> 2, wn = w & 3;
    const int row0 = blockIdx.x * 256;
    const int col0 = blockIdx.y * 128;
    const int z = blockIdx.z;

    float* C = (z == 0) ? C0 : (z == 1) ? C1 : C2;
    const float* bias = (z == 0) ? bias0 : (z == 1) ? bias1 : bias2;

    const __nv_bfloat16* A_h = Ah + (size_t)row0 * K;
    const __nv_bfloat16* A_l = Al + (size_t)row0 * K;
    size_t Boff = (size_t)(z * nbz + blockIdx.y) * 128 * K;
    const __nv_bfloat16* B_h = Bth + Boff;
    const __nv_bfloat16* B_l = Btl + Boff;

    const uint32_t aoff = (uint32_t)((wm * 64 + (l & 15)) * ROWB + (l >> 4) * 16);
    const uint32_t boff = (uint32_t)((wn * 32 + (l & 7) + ((l >> 4) & 1) * 8) * ROWB
                                     + ((l >> 3) & 1) * 16);

    float acc[4][4][4];
#pragma unroll
    for (int mt = 0; mt < 4; mt++)
#pragma unroll
        for (int nt = 0; nt < 4; nt++)
#pragma unroll
            for (int j = 0; j < 4; j++) acc[mt][nt][j] = 0.f;

    const int nch = K >> 6;
    load_stage(sb, 0, 0, A_h, A_l, B_h, B_l, K, t);

    for (int c = 0; c < nch; c++) {
        if (c + 1 < nch) {
            load_stage(sb, (c + 1) & 1, (c + 1) << 6, A_h, A_l, B_h, B_l, K, t);
            asm volatile("cp.async.wait_group 1;" ::: "memory");
        } else {
            asm volatile("cp.async.wait_group 0;" ::: "memory");
        }
        __syncthreads();

        uint32_t Abase = sb + (c & 1) * STAGEB;
        uint32_t Bbase = Abase + B_BASE;
#pragma unroll
        for (int ks = 0; ks < 4; ks++) {
            uint32_t bh[2][4], bl[2][4];
#pragma unroll
            for (int p = 0; p < 2; p++) {
                ldsm4(bh[p], Bbase + boff + p * 2304 + ks * 32);
                ldsm4(bl[p], Bbase + B_MAT + boff + p * 2304 + ks * 32);
            }
#pragma unroll
            for (int mt = 0; mt < 4; mt++) {
                uint32_t ah[4], al[4];
                ldsm4(ah, Abase + aoff + mt * 2304 + ks * 32);
                ldsm4(al, Abase + A_MAT + aoff + mt * 2304 + ks * 32);
#pragma unroll
                for (int nt = 0; nt < 4; nt++) {
                    float* cc = acc[mt][nt];
                    const uint32_t* bph = &bh[nt >> 1][(nt & 1) * 2];
                    const uint32_t* bpl = &bl[nt >> 1][(nt & 1) * 2];
                    mma16816(cc, ah, bph);
                    mma16816(cc, al, bph);
                    mma16816(cc, ah, bpl);
                }
            }
        }
        __syncthreads();
    }

    const int rl = l >> 2;
    const int cl = (l & 3) * 2;
#pragma unroll
    for (int mt = 0; mt < 4; mt++) {
#pragma unroll
        for (int rh = 0; rh < 2; rh++) {
            int r = row0 + wm * 64 + mt * 16 + rh * 8 + rl;
#pragma unroll
            for (int nt = 0; nt < 4; nt++) {
                int cix = col0 + wn * 32 + nt * 8 + cl;
                float v0 = acc[mt][nt][rh * 2 + 0];
                float v1 = acc[mt][nt][rh * 2 + 1];
                if (bias) { v0 += bias[cix]; v1 += bias[cix + 1]; }
                if (C) {
                    *(float2*)(C + (size_t)r * ldc + cix) = make_float2(v0, v1);
                } else {
                    __nv_bfloat16 h0 = __float2bfloat16_rn(v0);
                    __nv_bfloat16 h1 = __float2bfloat16_rn(v1);
                    size_t ui = ((size_t)r * ldc + cix) >> 1;
                    __nv_bfloat162 hp; hp.x = h0; hp.y = h1;
                    ((uint32_t*)Ch)[ui] = *reinterpret_cast<uint32_t*>(&hp);
                    ((uint32_t*)Cl)[ui] = pack_bf2(v0 - __bfloat162float(h0),
                                                   v1 - __bfloat162float(h1));
                }
            }
        }
    }
}

// ---------------------------------------------------------------------------
// producers
// ---------------------------------------------------------------------------
__global__ void norm_split(const float* __restrict__ emb,
                           __nv_bfloat16* __restrict__ Ah, __nv_bfloat16* __restrict__ Al) {
    int gw = (blockIdx.x * blockDim.x + threadIdx.x) >> 5;
    if (gw >= NODES) return;
    int lane = threadIdx.x & 31;
    float4 v = ((const float4*)(emb + (size_t)gw * EDIM))[lane];
    float ss = v.x * v.x + v.y * v.y + v.z * v.z + v.w * v.w;
#pragma unroll
    for (int o = 16; o > 0; o >>= 1) ss += __shfl_xor_sync(0xffffffffu, ss, o);
    float inv = 1.0f / fmaxf(sqrtf(ss), 1e-12f);
    v.x *= inv; v.y *= inv; v.z *= inv; v.w *= inv;
    __nv_bfloat16 hx = __float2bfloat16_rn(v.x), hy = __float2bfloat16_rn(v.y);
    __nv_bfloat16 hz = __float2bfloat16_rn(v.z), hw = __float2bfloat16_rn(v.w);
    size_t ui = ((size_t)gw * EDIM + lane * 4) >> 1;
    __nv_bfloat162 p0; p0.x = hx; p0.y = hy;
    __nv_bfloat162 p1; p1.x = hz; p1.y = hw;
    ((uint32_t*)Ah)[ui]     = *reinterpret_cast<uint32_t*>(&p0);
    ((uint32_t*)Ah)[ui + 1] = *reinterpret_cast<uint32_t*>(&p1);
    ((uint32_t*)Al)[ui]     = pack_bf2(v.x - __bfloat162float(hx), v.y - __bfloat162float(hy));
    ((uint32_t*)Al)[ui + 1] = pack_bf2(v.z - __bfloat162float(hz), v.w - __bfloat162float(hw));
}

__global__ void zero_pad(__nv_bfloat16* Ah, __nv_bfloat16* Al, int K) {
    int n = (MPAD - NODES) * K / 2;
    int i = blockIdx.x * blockDim.x + threadIdx.x;
    if (i < n) {
        ((uint32_t*)(Ah + (size_t)NODES * K))[i] = 0;
        ((uint32_t*)(Al + (size_t)NODES * K))[i] = 0;
    }
}

__global__ void split_bt_proj(const float* __restrict__ W) {
    int idx = blockIdx.x * blockDim.x + threadIdx.x;
    if (idx >= EDIM * PDIM) return;
    int k = idx / PDIM, n = idx % PDIM;
    float v = W[idx];
    __nv_bfloat16 h = __float2bfloat16_rn(v);
    g_Bth[(size_t)n * EDIM + k] = h;
    g_Btl[(size_t)n * EDIM + k] = __float2bfloat16_rn(v - __bfloat162float(h));
}

__global__ void split_bt_layer(const float* __restrict__ bases, const float* __restrict__ root, int K) {
    int z = blockIdx.z;
    const float* in = (z < 2) ? bases + (size_t)z * K * HID : root;
    int idx = blockIdx.x * blockDim.x + threadIdx.x;
    if (idx >= K * HID) return;
    int k = idx / HID, n = idx % HID;
    float v = in[idx];
    __nv_bfloat16 h = __float2bfloat16_rn(v);
    size_t o = ((size_t)z * HID + n) * K + k;
    g_Bth[o] = h;
    g_Btl[o] = __float2bfloat16_rn(v - __bfloat162float(h));
}

// ---------------------------------------------------------------------------
// CSR build (once per launch)
// ---------------------------------------------------------------------------
__global__ void zero_counts() {
    int i = blockIdx.x * blockDim.x + threadIdx.x;
    if (i < NODES * NREL) g_cnt[i] = 0;
    if (i < NODES) { g_cntnode[i] = 0; g_fill[i] = 0; }
}
__global__ void count_edges(const int* __restrict__ dst, const int* __restrict__ et) {
    int e = blockIdx.x * blockDim.x + threadIdx.x;
    if (e < NEDGE) {
        int d = dst[e];
        atomicAdd(&g_cnt[d * NREL + et[e]], 1);
        atomicAdd(&g_cntnode[d], 1);
    }
}
__global__ void scan1() {    // SCANB blocks x 256: per-block inclusive scan
    __shared__ int sh[256];
    int t = threadIdx.x;
    int idx = blockIdx.x * 256 + t;
    int v = (idx < NODES) ? g_cntnode[idx] : 0;
    sh[t] = v;
    __syncthreads();
#pragma unroll
    for (int o = 1; o < 256; o <<= 1) {
        int x = (t >= o) ? sh[t - o] : 0;
        __syncthreads();
        sh[t] += x;
        __syncthreads();
    }
    if (idx < NODES) g_rowptr[idx + 1] = sh[t];
    if (t == 255) g_blksum[blockIdx.x] = sh[255];
}
__global__ void scan2() {    // 1 thread: exclusive scan of block sums
    int run = 0;
    for (int b = 0; b < SCANB; b++) {
        int v = g_blksum[b];
        g_blksum[b] = run;
        run += v;
    }
    g_rowptr[0] = 0;
}
__global__ void scan3() {
    int idx = blockIdx.x * blockDim.x + threadIdx.x;
    if (idx < NODES) g_rowptr[idx + 1] += g_blksum[idx >> 8];
}
__global__ void scatter_edges(const int* __restrict__ src, const int* __restrict__ dst,
                              const int* __restrict__ et) {
    int e = blockIdx.x * blockDim.x + threadIdx.x;
    if (e >= NEDGE) return;
    int d = dst[e], r = et[e], s = src[e];
    int pos = g_rowptr[d] + atomicAdd(&g_fill[d], 1);
    g_packed[pos] = s | (r << 24);
    int c = g_cnt[d * NREL + r];
    g_invw[pos] = 1.0f / (float)(c > 0 ? c : 1);
}

// ---------------------------------------------------------------------------
// gather aggregation: buf[d] += sum_e invw*(c0*h0[src] + c1*h1[src]), no atomics
// one warp per (node, 128-col half)
// ---------------------------------------------------------------------------
__global__ void __launch_bounds__(256) csr_agg(const float* __restrict__ comp) {
    int gw = (blockIdx.x * blockDim.x + threadIdx.x) >> 5;
    if (gw >= NODES * 2) return;
    int d = gw >> 1;
    int lane = threadIdx.x & 31;
    int col = (gw & 1) * 128 + lane * 4;
    int beg = g_rowptr[d], end = g_rowptr[d + 1];
    float* bp = &g_buf[(size_t)d * HID + col];
    float4 acc = *(float4*)bp;
    for (int e = beg; e < end; e++) {
        int pk = __ldg(&g_packed[e]);
        float w = __ldg(&g_invw[e]);
        int s = pk & 0xFFFFFF;
        int r = pk >> 24;
        float c0 = comp[2 * r] * w;
        float c1 = comp[2 * r + 1] * w;
        float4 a = *(const float4*)&g_h0[(size_t)s * HID + col];
        float4 b = *(const float4*)&g_h1[(size_t)s * HID + col];
        acc.x += c0 * a.x + c1 * b.x;
        acc.y += c0 * a.y + c1 * b.y;
        acc.z += c0 * a.z + c1 * b.z;
        acc.w += c0 * a.w + c1 * b.w;
    }
    *(float4*)bp = acc;
}

// ---------------------------------------------------------------------------
// batchnorm
// ---------------------------------------------------------------------------
__global__ void zero_stats() {
    int c = threadIdx.x;
    g_sum[c] = 0.f; g_sumsq[c] = 0.f;
}
__global__ void bn_stats() {
    int c = threadIdx.x;
    float s = 0.f, ss = 0.f;
    for (int r = blockIdx.x; r < NODES; r += gridDim.x) {
        float v = g_buf[(size_t)r * HID + c];
        s += v; ss += v * v;
    }
    atomicAdd(&g_sum[c], s);
    atomicAdd(&g_sumsq[c], ss);
}
__global__ void bn_finalize(const float* __restrict__ gamma, const float* __restrict__ beta) {
    int c = threadIdx.x;
    const float invM = 1.0f / (float)NODES;
    float mean = g_sum[c] * invM;
    float var = g_sumsq[c] * invM - mean * mean;
    float sc = gamma[c] * rsqrtf(var + BN_EPS);
    g_scale[c] = sc;
    g_shift[c] = beta[c] - mean * sc;
}
__global__ void bn_apply_f32(float* __restrict__ out) {
    int idx = blockIdx.x * blockDim.x + threadIdx.x;
    if (idx >= NODES * HID / 4) return;
    int c4 = (idx & 63) << 2;
    float4 v = ((const float4*)g_buf)[idx];
    float4 sc = *(const float4*)&g_scale[c4];
    float4 sh = *(const float4*)&g_shift[c4];
    v.x = fmaxf(fmaf(v.x, sc.x, sh.x), 0.f);
    v.y = fmaxf(fmaf(v.y, sc.y, sh.y), 0.f);
    v.z = fmaxf(fmaf(v.z, sc.z, sh.z), 0.f);
    v.w = fmaxf(fmaf(v.w, sc.w, sh.w), 0.f);
    ((float4*)out)[idx] = v;
}
__global__ void bn_apply_split(__nv_bfloat16* __restrict__ Ah, __nv_bfloat16* __restrict__ Al) {
    int idx = blockIdx.x * blockDim.x + threadIdx.x;
    if (idx >= NODES * HID / 4) return;
    int c4 = (idx & 63) << 2;
    float4 v = ((const float4*)g_buf)[idx];
    float4 sc = *(const float4*)&g_scale[c4];
    float4 sh = *(const float4*)&g_shift[c4];
    v.x = fmaxf(fmaf(v.x, sc.x, sh.x), 0.f);
    v.y = fmaxf(fmaf(v.y, sc.y, sh.y), 0.f);
    v.z = fmaxf(fmaf(v.z, sc.z, sh.z), 0.f);
    v.w = fmaxf(fmaf(v.w, sc.w, sh.w), 0.f);
    __nv_bfloat16 hx = __float2bfloat16_rn(v.x), hy = __float2bfloat16_rn(v.y);
    __nv_bfloat16 hz = __float2bfloat16_rn(v.z), hw = __float2bfloat16_rn(v.w);
    __nv_bfloat162 p0; p0.x = hx; p0.y = hy;
    __nv_bfloat162 p1; p1.x = hz; p1.y = hw;
    ((uint32_t*)Ah)[idx * 2]     = *reinterpret_cast<uint32_t*>(&p0);
    ((uint32_t*)Ah)[idx * 2 + 1] = *reinterpret_cast<uint32_t*>(&p1);
    ((uint32_t*)Al)[idx * 2]     = pack_bf2(v.x - __bfloat162float(hx), v.y - __bfloat162float(hy));
    ((uint32_t*)Al)[idx * 2 + 1] = pack_bf2(v.z - __bfloat162float(hz), v.w - __bfloat162float(hw));
}

// ---------------------------------------------------------------------------
// host launch
// ---------------------------------------------------------------------------
extern "C" void kernel_launch(void* const* d_in, const int* in_sizes, int n_in,
                              void* d_out, int out_size) {
    const int* edge_index = (const int*)d_in[0];
    const int* src = edge_index;
    const int* dst = edge_index + NEDGE;
    const int* etype = (const int*)d_in[1];
    const float* emb = (const float*)d_in[2];
    const float* proj_w = (const float*)d_in[3];
    const float* proj_b = (const float*)d_in[4];

    const float *comp[3], *bases[3], *root[3], *bias[3], *gamma[3], *beta[3];
    for (int l = 0; l < 3; l++) {
        comp[l]  = (const float*)d_in[5 + 6 * l];
        bases[l] = (const float*)d_in[6 + 6 * l];
        root[l]  = (const float*)d_in[7 + 6 * l];
        bias[l]  = (const float*)d_in[8 + 6 * l];
        gamma[l] = (const float*)d_in[9 + 6 * l];
        beta[l]  = (const float*)d_in[10 + 6 * l];
    }

    __nv_bfloat16 *Ah0, *Al0, *Ah1, *Al1, *Bth, *Btl;
    float *h0, *h1, *buf;
    cudaGetSymbolAddress((void**)&Ah0, g_Ah0);
    cudaGetSymbolAddress((void**)&Al0, g_Al0);
    cudaGetSymbolAddress((void**)&Ah1, g_Ah1);
    cudaGetSymbolAddress((void**)&Al1, g_Al1);
    cudaGetSymbolAddress((void**)&Bth, g_Bth);
    cudaGetSymbolAddress((void**)&Btl, g_Btl);
    cudaGetSymbolAddress((void**)&h0, g_h0);
    cudaGetSymbolAddress((void**)&h1, g_h1);
    cudaGetSymbolAddress((void**)&buf, g_buf);

    cudaFuncSetAttribute(gemm_mma, cudaFuncAttributeMaxDynamicSharedMemorySize, SMEM_GEMM);

    // normalize + split -> set0 (K=128)
    norm_split<<<(NODES * 32 + 255) / 256, 256>>>(emb, Ah0, Al0);
    zero_pad<<<((MPAD - NODES) * EDIM / 2 + 255) / 256, 256>>>(Ah0, Al0, EDIM);
    split_bt_proj<<<(EDIM * PDIM + 255) / 256, 256>>>(proj_w);

    // CSR build (shared by all 3 layers)
    zero_counts<<<(NODES * NREL + 255) / 256, 256>>>();
    count_edges<<<(NEDGE + 255) / 256, 256>>>(dst, etype);
    scan1<<<SCANB, 256>>>();
    scan2<<<1, 1>>>();
    scan3<<<(NODES + 255) / 256, 256>>>();
    scatter_edges<<<(NEDGE + 255) / 256, 256>>>(src, dst, etype);

    // proj GEMM -> split output into set1 (K=768 for layer0), bias fused
    {
        dim3 grid(MBLK, 6, 1);
        gemm_mma<<<grid, 512, SMEM_GEMM>>>(
            Ah0, Al0, EDIM, 6, Bth, Btl,
            nullptr, nullptr, nullptr, PDIM,
            proj_b, proj_b, proj_b,
            Ah1, Al1);
    }

    for (int l = 0; l < 3; l++) {
        int K = (l == 0) ? PDIM : HID;
        __nv_bfloat16* Ah = (l == 1) ? Ah0 : Ah1;   // l0:set1, l1:set0, l2:set1
        __nv_bfloat16* Al = (l == 1) ? Al0 : Al1;

        zero_pad<<<((MPAD - NODES) * K / 2 + 255) / 256, 256>>>(Ah, Al, K);
        {
            dim3 g((K * HID + 255) / 256, 1, 3);
            split_bt_layer<<<g, 256>>>(bases[l], root[l], K);
        }
        {
            dim3 grid(MBLK, 2, 3);
            gemm_mma<<<grid, 512, SMEM_GEMM>>>(
                Ah, Al, K, 2, Bth, Btl,
                h0, h1, buf, HID,
                nullptr, nullptr, bias[l],
                nullptr, nullptr);
        }

        // gather aggregation, no atomics
        csr_agg<<<(NODES * 2 * 32 + 255) / 256, 256>>>(comp[l]);

        zero_stats<<<1, HID>>>();
        bn_stats<<<256, HID>>>();
        bn_finalize<<<1, HID>>>(gamma[l], beta[l]);
        if (l < 2) {
            __nv_bfloat16* oAh = (l == 0) ? Ah0 : Ah1;
            __nv_bfloat16* oAl = (l == 0) ? Al0 : Al1;
            bn_apply_split<<<(NODES * HID / 4 + 255) / 256, 256>>>(oAh, oAl);
        } else {
            bn_apply_f32<<<(NODES * HID / 4 + 255) / 256, 256>>>((float*)d_out);
        }
    }
}

// round 6
// speedup vs baseline: 2.4329x; 1.1533x over previous
#include <cuda_runtime.h>
#include <cuda_bf16.h>
#include <cstdint>

#define NODES 50000
#define MPAD  50176          // 196 * 256
#define EDIM  128
#define PDIM  768
#define HID   256
#define NREL  16
#define NEDGE 400000
#define BN_EPS 1e-5f
#define MBLK  196            // MPAD / 256
#define SCANB 196
#define PADR  (MPAD - NODES) // 176

// ---------------------------------------------------------------------------
// scratch (static device memory; no allocations)
// ---------------------------------------------------------------------------
__device__ __nv_bfloat16 g_Ah0[(size_t)MPAD * PDIM];
__device__ __nv_bfloat16 g_Al0[(size_t)MPAD * PDIM];
__device__ __nv_bfloat16 g_Ah1[(size_t)MPAD * PDIM];
__device__ __nv_bfloat16 g_Al1[(size_t)MPAD * PDIM];
__device__ __nv_bfloat16 g_Bth[3 * 256 * 768];
__device__ __nv_bfloat16 g_Btl[3 * 256 * 768];
__device__ float g_h0[(size_t)MPAD * HID];
__device__ float g_h1[(size_t)MPAD * HID];
__device__ float g_buf[(size_t)MPAD * HID];
__device__ int   g_cnt[NODES * NREL];
__device__ int   g_cntnode[NODES];
__device__ int   g_fill[NODES];
__device__ int   g_rowptr[NODES + 1];
__device__ int   g_blksum[SCANB];
__device__ int   g_packed[NEDGE];
__device__ float g_invw[NEDGE];
__device__ float g_sum[HID], g_sumsq[HID], g_scale[HID], g_shift[HID];

// ---------------------------------------------------------------------------
// helpers
// ---------------------------------------------------------------------------
__device__ __forceinline__ uint32_t smem_u32(const void* p) {
    uint32_t a;
    asm("{ .reg .u64 t; cvta.to.shared.u64 t, %1; cvt.u32.u64 %0, t; }" : "=r"(a) : "l"(p));
    return a;
}
__device__ __forceinline__ void cp16(uint32_t dst, const void* src) {
    asm volatile("cp.async.cg.shared.global [%0], [%1], 16;" :: "r"(dst), "l"(src) : "memory");
}
__device__ __forceinline__ void ldsm4(uint32_t* r, uint32_t addr) {
    asm volatile("ldmatrix.sync.aligned.m8n8.x4.shared.b16 {%0,%1,%2,%3}, [%4];"
                 : "=r"(r[0]), "=r"(r[1]), "=r"(r[2]), "=r"(r[3]) : "r"(addr));
}
__device__ __forceinline__ void mma16816(float* c, const uint32_t* a, const uint32_t* b) {
    asm volatile("mma.sync.aligned.m16n8k16.row.col.f32.bf16.bf16.f32 "
                 "{%0,%1,%2,%3}, {%4,%5,%6,%7}, {%8,%9}, {%0,%1,%2,%3};"
                 : "+f"(c[0]), "+f"(c[1]), "+f"(c[2]), "+f"(c[3])
                 : "r"(a[0]), "r"(a[1]), "r"(a[2]), "r"(a[3]), "r"(b[0]), "r"(b[1]));
}
static __device__ __forceinline__ uint32_t pack_bf2(float a, float b) {
    __nv_bfloat162 t;
    t.x = __float2bfloat16_rn(a);
    t.y = __float2bfloat16_rn(b);
    return *reinterpret_cast<uint32_t*>(&t);
}

#define ROWB    144
#define A_MAT   36864
#define B_MAT   18432
#define B_BASE  73728
#define STAGEB  110592
#define SMEM_GEMM (2 * STAGEB)

// ---------------------------------------------------------------------------
// split-bf16 GEMM via mma.sync (unchanged from round 5 — proven)
// ---------------------------------------------------------------------------
__device__ __forceinline__ void load_stage(
    uint32_t sb, int stage, int k0,
    const __nv_bfloat16* __restrict__ Ah, const __nv_bfloat16* __restrict__ Al,
    const __nv_bfloat16* __restrict__ Bh, const __nv_bfloat16* __restrict__ Bl,
    int K, int t)
{
    uint32_t base = sb + stage * STAGEB;
#pragma unroll
    for (int i = 0; i < 4; i++) {
        int unit = t + i * 512;
        int r = unit >> 3, u = unit & 7;
        uint32_t off = r * ROWB + u * 16;
        cp16(base + off,         Ah + (size_t)r * K + k0 + u * 8);
        cp16(base + A_MAT + off, Al + (size_t)r * K + k0 + u * 8);
    }
#pragma unroll
    for (int i = 0; i < 2; i++) {
        int unit = t + i * 512;
        int r = unit >> 3, u = unit & 7;
        uint32_t off = r * ROWB + u * 16;
        cp16(base + B_BASE + off,         Bh + (size_t)r * K + k0 + u * 8);
        cp16(base + B_BASE + B_MAT + off, Bl + (size_t)r * K + k0 + u * 8);
    }
    asm volatile("cp.async.commit_group;" ::: "memory");
}

__global__ void __launch_bounds__(512, 1) gemm_mma(
    const __nv_bfloat16* __restrict__ Ah, const __nv_bfloat16* __restrict__ Al,
    int K, int nbz,
    const __nv_bfloat16* __restrict__ Bth, const __nv_bfloat16* __restrict__ Btl,
    float* C0, float* C1, float* C2, int ldc,
    const float* bias0, const float* bias1, const float* bias2,
    __nv_bfloat16* Ch, __nv_bfloat16* Cl)
{
    extern __shared__ char smem[];
    uint32_t sb = smem_u32(smem);
    const int t = threadIdx.x;
    const int w = t >> 5, l = t & 31;
    const int wm = w >> 2, wn = w & 3;
    const int row0 = blockIdx.x * 256;
    const int col0 = blockIdx.y * 128;
    const int z = blockIdx.z;

    float* C = (z == 0) ? C0 : (z == 1) ? C1 : C2;
    const float* bias = (z == 0) ? bias0 : (z == 1) ? bias1 : bias2;

    const __nv_bfloat16* A_h = Ah + (size_t)row0 * K;
    const __nv_bfloat16* A_l = Al + (size_t)row0 * K;
    size_t Boff = (size_t)(z * nbz + blockIdx.y) * 128 * K;
    const __nv_bfloat16* B_h = Bth + Boff;
    const __nv_bfloat16* B_l = Btl + Boff;

    const uint32_t aoff = (uint32_t)((wm * 64 + (l & 15)) * ROWB + (l >> 4) * 16);
    const uint32_t boff = (uint32_t)((wn * 32 + (l & 7) + ((l >> 4) & 1) * 8) * ROWB
                                     + ((l >> 3) & 1) * 16);

    float acc[4][4][4];
#pragma unroll
    for (int mt = 0; mt < 4; mt++)
#pragma unroll
        for (int nt = 0; nt < 4; nt++)
#pragma unroll
            for (int j = 0; j < 4; j++) acc[mt][nt][j] = 0.f;

    const int nch = K >> 6;
    load_stage(sb, 0, 0, A_h, A_l, B_h, B_l, K, t);

    for (int c = 0; c < nch; c++) {
        if (c + 1 < nch) {
            load_stage(sb, (c + 1) & 1, (c + 1) << 6, A_h, A_l, B_h, B_l, K, t);
            asm volatile("cp.async.wait_group 1;" ::: "memory");
        } else {
            asm volatile("cp.async.wait_group 0;" ::: "memory");
        }
        __syncthreads();

        uint32_t Abase = sb + (c & 1) * STAGEB;
        uint32_t Bbase = Abase + B_BASE;
#pragma unroll
        for (int ks = 0; ks < 4; ks++) {
            uint32_t bh[2][4], bl[2][4];
#pragma unroll
            for (int p = 0; p < 2; p++) {
                ldsm4(bh[p], Bbase + boff + p * 2304 + ks * 32);
                ldsm4(bl[p], Bbase + B_MAT + boff + p * 2304 + ks * 32);
            }
#pragma unroll
            for (int mt = 0; mt < 4; mt++) {
                uint32_t ah[4], al[4];
                ldsm4(ah, Abase + aoff + mt * 2304 + ks * 32);
                ldsm4(al, Abase + A_MAT + aoff + mt * 2304 + ks * 32);
#pragma unroll
                for (int nt = 0; nt < 4; nt++) {
                    float* cc = acc[mt][nt];
                    const uint32_t* bph = &bh[nt >> 1][(nt & 1) * 2];
                    const uint32_t* bpl = &bl[nt >> 1][(nt & 1) * 2];
                    mma16816(cc, ah, bph);
                    mma16816(cc, al, bph);
                    mma16816(cc, ah, bpl);
                }
            }
        }
        __syncthreads();
    }

    const int rl = l >> 2;
    const int cl = (l & 3) * 2;
#pragma unroll
    for (int mt = 0; mt < 4; mt++) {
#pragma unroll
        for (int rh = 0; rh < 2; rh++) {
            int r = row0 + wm * 64 + mt * 16 + rh * 8 + rl;
#pragma unroll
            for (int nt = 0; nt < 4; nt++) {
                int cix = col0 + wn * 32 + nt * 8 + cl;
                float v0 = acc[mt][nt][rh * 2 + 0];
                float v1 = acc[mt][nt][rh * 2 + 1];
                if (bias) { v0 += bias[cix]; v1 += bias[cix + 1]; }
                if (C) {
                    *(float2*)(C + (size_t)r * ldc + cix) = make_float2(v0, v1);
                } else {
                    __nv_bfloat16 h0 = __float2bfloat16_rn(v0);
                    __nv_bfloat16 h1 = __float2bfloat16_rn(v1);
                    size_t ui = ((size_t)r * ldc + cix) >> 1;
                    __nv_bfloat162 hp; hp.x = h0; hp.y = h1;
                    ((uint32_t*)Ch)[ui] = *reinterpret_cast<uint32_t*>(&hp);
                    ((uint32_t*)Cl)[ui] = pack_bf2(v0 - __bfloat162float(h0),
                                                   v1 - __bfloat162float(h1));
                }
            }
        }
    }
}

// ---------------------------------------------------------------------------
// producers
// ---------------------------------------------------------------------------
__global__ void norm_split(const float* __restrict__ emb,
                           __nv_bfloat16* __restrict__ Ah, __nv_bfloat16* __restrict__ Al) {
    int gw = (blockIdx.x * blockDim.x + threadIdx.x) >> 5;
    if (gw >= NODES) return;
    int lane = threadIdx.x & 31;
    float4 v = ((const float4*)(emb + (size_t)gw * EDIM))[lane];
    float ss = v.x * v.x + v.y * v.y + v.z * v.z + v.w * v.w;
#pragma unroll
    for (int o = 16; o > 0; o >>= 1) ss += __shfl_xor_sync(0xffffffffu, ss, o);
    float inv = 1.0f / fmaxf(sqrtf(ss), 1e-12f);
    v.x *= inv; v.y *= inv; v.z *= inv; v.w *= inv;
    __nv_bfloat16 hx = __float2bfloat16_rn(v.x), hy = __float2bfloat16_rn(v.y);
    __nv_bfloat16 hz = __float2bfloat16_rn(v.z), hw = __float2bfloat16_rn(v.w);
    size_t ui = ((size_t)gw * EDIM + lane * 4) >> 1;
    __nv_bfloat162 p0; p0.x = hx; p0.y = hy;
    __nv_bfloat162 p1; p1.x = hz; p1.y = hw;
    ((uint32_t*)Ah)[ui]     = *reinterpret_cast<uint32_t*>(&p0);
    ((uint32_t*)Ah)[ui + 1] = *reinterpret_cast<uint32_t*>(&p1);
    ((uint32_t*)Al)[ui]     = pack_bf2(v.x - __bfloat162float(hx), v.y - __bfloat162float(hy));
    ((uint32_t*)Al)[ui + 1] = pack_bf2(v.z - __bfloat162float(hz), v.w - __bfloat162float(hw));
}

// zero ALL pad regions once (pad rows are never rewritten afterwards):
// region 0: set0 K=128, region 1: set0 K=256, region 2: set1 K=768, region 3: set1 K=256
__global__ void zero_pads_all() {
    const int Ks[4] = {128, 256, 768, 256};
    int reg = blockIdx.y;
    int K = Ks[reg];
    int n = PADR * K / 2;                 // uint32 count
    int i = blockIdx.x * blockDim.x + threadIdx.x;
    if (i >= n) return;
    size_t base = (size_t)NODES * K / 2;  // uint32 offset
    if (reg < 2) {
        ((uint32_t*)g_Ah0)[base + i] = 0;
        ((uint32_t*)g_Al0)[base + i] = 0;
    } else {
        ((uint32_t*)g_Ah1)[base + i] = 0;
        ((uint32_t*)g_Al1)[base + i] = 0;
    }
}

__global__ void split_bt_proj(const float* __restrict__ W) {
    int idx = blockIdx.x * blockDim.x + threadIdx.x;
    if (idx >= EDIM * PDIM) return;
    int k = idx / PDIM, n = idx % PDIM;
    float v = W[idx];
    __nv_bfloat16 h = __float2bfloat16_rn(v);
    g_Bth[(size_t)n * EDIM + k] = h;
    g_Btl[(size_t)n * EDIM + k] = __float2bfloat16_rn(v - __bfloat162float(h));
}

// also zeroes BN stat accumulators (runs before csr_agg_bn each layer)
__global__ void split_bt_layer(const float* __restrict__ bases, const float* __restrict__ root, int K) {
    int z = blockIdx.z;
    int idx = blockIdx.x * blockDim.x + threadIdx.x;
    if (z == 0 && blockIdx.x == 0 && threadIdx.x < HID) {
        g_sum[threadIdx.x] = 0.f;
        g_sumsq[threadIdx.x] = 0.f;
    }
    const float* in = (z < 2) ? bases + (size_t)z * K * HID : root;
    if (idx >= K * HID) return;
    int k = idx / HID, n = idx % HID;
    float v = in[idx];
    __nv_bfloat16 h = __float2bfloat16_rn(v);
    size_t o = ((size_t)z * HID + n) * K + k;
    g_Bth[o] = h;
    g_Btl[o] = __float2bfloat16_rn(v - __bfloat162float(h));
}

// ---------------------------------------------------------------------------
// CSR build (once per launch)
// ---------------------------------------------------------------------------
__global__ void zero_counts() {
    int i = blockIdx.x * blockDim.x + threadIdx.x;
    if (i < NODES * NREL) g_cnt[i] = 0;
    if (i < NODES) { g_cntnode[i] = 0; g_fill[i] = 0; }
}
__global__ void count_edges(const int* __restrict__ dst, const int* __restrict__ et) {
    int e = blockIdx.x * blockDim.x + threadIdx.x;
    if (e < NEDGE) {
        int d = dst[e];
        atomicAdd(&g_cnt[d * NREL + et[e]], 1);
        atomicAdd(&g_cntnode[d], 1);
    }
}
__global__ void scan1() {
    __shared__ int sh[256];
    int t = threadIdx.x;
    int idx = blockIdx.x * 256 + t;
    int v = (idx < NODES) ? g_cntnode[idx] : 0;
    sh[t] = v;
    __syncthreads();
#pragma unroll
    for (int o = 1; o < 256; o <<= 1) {
        int x = (t >= o) ? sh[t - o] : 0;
        __syncthreads();
        sh[t] += x;
        __syncthreads();
    }
    if (idx < NODES) g_rowptr[idx + 1] = sh[t];
    if (t == 255) g_blksum[blockIdx.x] = sh[255];
}
__global__ void scan2() {
    int run = 0;
    for (int b = 0; b < SCANB; b++) {
        int v = g_blksum[b];
        g_blksum[b] = run;
        run += v;
    }
    g_rowptr[0] = 0;
}
__global__ void scan3() {
    int idx = blockIdx.x * blockDim.x + threadIdx.x;
    if (idx < NODES) g_rowptr[idx + 1] += g_blksum[idx >> 8];
}
__global__ void scatter_edges(const int* __restrict__ src, const int* __restrict__ dst,
                              const int* __restrict__ et) {
    int e = blockIdx.x * blockDim.x + threadIdx.x;
    if (e >= NEDGE) return;
    int d = dst[e], r = et[e], s = src[e];
    int pos = g_rowptr[d] + atomicAdd(&g_fill[d], 1);
    g_packed[pos] = s | (r << 24);
    int c = g_cnt[d * NREL + r];
    g_invw[pos] = 1.0f / (float)(c > 0 ? c : 1);
}

// ---------------------------------------------------------------------------
// gather aggregation + fused BN statistics.
// one warp per node (full 256-col row, 8 accs/lane); per-lane BN partials
// accumulated across its nodes, reduced via smem, flushed per block.
// ---------------------------------------------------------------------------
#define AGG_BLOCKS 1184
__global__ void __launch_bounds__(256) csr_agg_bn(const float* __restrict__ comp) {
    __shared__ float s_sum[HID];
    __shared__ float s_sumsq[HID];
    __shared__ float s_comp[2 * NREL];
    int t = threadIdx.x;
    if (t < 2 * NREL) s_comp[t] = comp[t];
    s_sum[t] = 0.f;
    s_sumsq[t] = 0.f;
    __syncthreads();

    int lane = t & 31, wid = t >> 5;
    float bsum[8], bsq[8];
#pragma unroll
    for (int i = 0; i < 8; i++) { bsum[i] = 0.f; bsq[i] = 0.f; }

    for (int d = blockIdx.x * 8 + wid; d < NODES; d += AGG_BLOCKS * 8) {
        int beg = g_rowptr[d], end = g_rowptr[d + 1];
        float* bp = &g_buf[(size_t)d * HID];
        float4 acc0 = ((float4*)bp)[lane];
        float4 acc1 = ((float4*)bp)[lane + 32];
        for (int e = beg; e < end; e++) {
            int pk = __ldg(&g_packed[e]);
            float w = __ldg(&g_invw[e]);
            int s = pk & 0xFFFFFF;
            int r = pk >> 24;
            float c0 = s_comp[2 * r] * w;
            float c1 = s_comp[2 * r + 1] * w;
            const float4* h0p = (const float4*)&g_h0[(size_t)s * HID];
            const float4* h1p = (const float4*)&g_h1[(size_t)s * HID];
            float4 a0 = h0p[lane],      b0 = h1p[lane];
            float4 a1 = h0p[lane + 32], b1 = h1p[lane + 32];
            acc0.x += c0 * a0.x + c1 * b0.x;
            acc0.y += c0 * a0.y + c1 * b0.y;
            acc0.z += c0 * a0.z + c1 * b0.z;
            acc0.w += c0 * a0.w + c1 * b0.w;
            acc1.x += c0 * a1.x + c1 * b1.x;
            acc1.y += c0 * a1.y + c1 * b1.y;
            acc1.z += c0 * a1.z + c1 * b1.z;
            acc1.w += c0 * a1.w + c1 * b1.w;
        }
        ((float4*)bp)[lane] = acc0;
        ((float4*)bp)[lane + 32] = acc1;
        bsum[0] += acc0.x; bsq[0] += acc0.x * acc0.x;
        bsum[1] += acc0.y; bsq[1] += acc0.y * acc0.y;
        bsum[2] += acc0.z; bsq[2] += acc0.z * acc0.z;
        bsum[3] += acc0.w; bsq[3] += acc0.w * acc0.w;
        bsum[4] += acc1.x; bsq[4] += acc1.x * acc1.x;
        bsum[5] += acc1.y; bsq[5] += acc1.y * acc1.y;
        bsum[6] += acc1.z; bsq[6] += acc1.z * acc1.z;
        bsum[7] += acc1.w; bsq[7] += acc1.w * acc1.w;
    }

    // lane owns cols lane*4+i (i<4) and 128+lane*4+i (i<4): distinct per warp
#pragma unroll
    for (int i = 0; i < 4; i++) {
        atomicAdd(&s_sum[lane * 4 + i], bsum[i]);
        atomicAdd(&s_sumsq[lane * 4 + i], bsq[i]);
        atomicAdd(&s_sum[128 + lane * 4 + i], bsum[4 + i]);
        atomicAdd(&s_sumsq[128 + lane * 4 + i], bsq[4 + i]);
    }
    __syncthreads();
    atomicAdd(&g_sum[t], s_sum[t]);
    atomicAdd(&g_sumsq[t], s_sumsq[t]);
}

// ---------------------------------------------------------------------------
// batchnorm finalize + apply
// ---------------------------------------------------------------------------
__global__ void bn_finalize(const float* __restrict__ gamma, const float* __restrict__ beta) {
    int c = threadIdx.x;
    const float invM = 1.0f / (float)NODES;
    float mean = g_sum[c] * invM;
    float var = g_sumsq[c] * invM - mean * mean;
    float sc = gamma[c] * rsqrtf(var + BN_EPS);
    g_scale[c] = sc;
    g_shift[c] = beta[c] - mean * sc;
}
__global__ void bn_apply_f32(float* __restrict__ out) {
    int idx = blockIdx.x * blockDim.x + threadIdx.x;
    if (idx >= NODES * HID / 4) return;
    int c4 = (idx & 63) << 2;
    float4 v = ((const float4*)g_buf)[idx];
    float4 sc = *(const float4*)&g_scale[c4];
    float4 sh = *(const float4*)&g_shift[c4];
    v.x = fmaxf(fmaf(v.x, sc.x, sh.x), 0.f);
    v.y = fmaxf(fmaf(v.y, sc.y, sh.y), 0.f);
    v.z = fmaxf(fmaf(v.z, sc.z, sh.z), 0.f);
    v.w = fmaxf(fmaf(v.w, sc.w, sh.w), 0.f);
    ((float4*)out)[idx] = v;
}
__global__ void bn_apply_split(__nv_bfloat16* __restrict__ Ah, __nv_bfloat16* __restrict__ Al) {
    int idx = blockIdx.x * blockDim.x + threadIdx.x;
    if (idx >= NODES * HID / 4) return;
    int c4 = (idx & 63) << 2;
    float4 v = ((const float4*)g_buf)[idx];
    float4 sc = *(const float4*)&g_scale[c4];
    float4 sh = *(const float4*)&g_shift[c4];
    v.x = fmaxf(fmaf(v.x, sc.x, sh.x), 0.f);
    v.y = fmaxf(fmaf(v.y, sc.y, sh.y), 0.f);
    v.z = fmaxf(fmaf(v.z, sc.z, sh.z), 0.f);
    v.w = fmaxf(fmaf(v.w, sc.w, sh.w), 0.f);
    __nv_bfloat16 hx = __float2bfloat16_rn(v.x), hy = __float2bfloat16_rn(v.y);
    __nv_bfloat16 hz = __float2bfloat16_rn(v.z), hw = __float2bfloat16_rn(v.w);
    __nv_bfloat162 p0; p0.x = hx; p0.y = hy;
    __nv_bfloat162 p1; p1.x = hz; p1.y = hw;
    ((uint32_t*)Ah)[idx * 2]     = *reinterpret_cast<uint32_t*>(&p0);
    ((uint32_t*)Ah)[idx * 2 + 1] = *reinterpret_cast<uint32_t*>(&p1);
    ((uint32_t*)Al)[idx * 2]     = pack_bf2(v.x - __bfloat162float(hx), v.y - __bfloat162float(hy));
    ((uint32_t*)Al)[idx * 2 + 1] = pack_bf2(v.z - __bfloat162float(hz), v.w - __bfloat162float(hw));
}

// ---------------------------------------------------------------------------
// host launch
// ---------------------------------------------------------------------------
extern "C" void kernel_launch(void* const* d_in, const int* in_sizes, int n_in,
                              void* d_out, int out_size) {
    const int* edge_index = (const int*)d_in[0];
    const int* src = edge_index;
    const int* dst = edge_index + NEDGE;
    const int* etype = (const int*)d_in[1];
    const float* emb = (const float*)d_in[2];
    const float* proj_w = (const float*)d_in[3];
    const float* proj_b = (const float*)d_in[4];

    const float *comp[3], *bases[3], *root[3], *bias[3], *gamma[3], *beta[3];
    for (int l = 0; l < 3; l++) {
        comp[l]  = (const float*)d_in[5 + 6 * l];
        bases[l] = (const float*)d_in[6 + 6 * l];
        root[l]  = (const float*)d_in[7 + 6 * l];
        bias[l]  = (const float*)d_in[8 + 6 * l];
        gamma[l] = (const float*)d_in[9 + 6 * l];
        beta[l]  = (const float*)d_in[10 + 6 * l];
    }

    __nv_bfloat16 *Ah0, *Al0, *Ah1, *Al1, *Bth, *Btl;
    float *h0, *h1, *buf;
    cudaGetSymbolAddress((void**)&Ah0, g_Ah0);
    cudaGetSymbolAddress((void**)&Al0, g_Al0);
    cudaGetSymbolAddress((void**)&Ah1, g_Ah1);
    cudaGetSymbolAddress((void**)&Al1, g_Al1);
    cudaGetSymbolAddress((void**)&Bth, g_Bth);
    cudaGetSymbolAddress((void**)&Btl, g_Btl);
    cudaGetSymbolAddress((void**)&h0, g_h0);
    cudaGetSymbolAddress((void**)&h1, g_h1);
    cudaGetSymbolAddress((void**)&buf, g_buf);

    cudaFuncSetAttribute(gemm_mma, cudaFuncAttributeMaxDynamicSharedMemorySize, SMEM_GEMM);

    norm_split<<<(NODES * 32 + 255) / 256, 256>>>(emb, Ah0, Al0);
    {
        dim3 g((PADR * 768 / 2 + 255) / 256, 4);
        zero_pads_all<<<g, 256>>>();
    }
    split_bt_proj<<<(EDIM * PDIM + 255) / 256, 256>>>(proj_w);

    // CSR build (shared by all 3 layers)
    zero_counts<<<(NODES * NREL + 255) / 256, 256>>>();
    count_edges<<<(NEDGE + 255) / 256, 256>>>(dst, etype);
    scan1<<<SCANB, 256>>>();
    scan2<<<1, 1>>>();
    scan3<<<(NODES + 255) / 256, 256>>>();
    scatter_edges<<<(NEDGE + 255) / 256, 256>>>(src, dst, etype);

    // proj GEMM -> split output into set1 (layer0 input, K=768), bias fused
    {
        dim3 grid(MBLK, 6, 1);
        gemm_mma<<<grid, 512, SMEM_GEMM>>>(
            Ah0, Al0, EDIM, 6, Bth, Btl,
            nullptr, nullptr, nullptr, PDIM,
            proj_b, proj_b, proj_b,
            Ah1, Al1);
    }

    for (int l = 0; l < 3; l++) {
        int K = (l == 0) ? PDIM : HID;
        __nv_bfloat16* Ah = (l == 1) ? Ah0 : Ah1;
        __nv_bfloat16* Al = (l == 1) ? Al0 : Al1;

        {
            dim3 g((K * HID + 255) / 256, 1, 3);
            split_bt_layer<<<g, 256>>>(bases[l], root[l], K);   // also zeroes BN stats
        }
        {
            dim3 grid(MBLK, 2, 3);
            gemm_mma<<<grid, 512, SMEM_GEMM>>>(
                Ah, Al, K, 2, Bth, Btl,
                h0, h1, buf, HID,
                nullptr, nullptr, bias[l],
                nullptr, nullptr);
        }
        csr_agg_bn<<<AGG_BLOCKS, 256>>>(comp[l]);   // aggregation + BN stats fused
        bn_finalize<<<1, HID>>>(gamma[l], beta[l]);
        if (l < 2) {
            __nv_bfloat16* oAh = (l == 0) ? Ah0 : Ah1;
            __nv_bfloat16* oAl = (l == 0) ? Al0 : Al1;
            bn_apply_split<<<(NODES * HID / 4 + 255) / 256, 256>>>(oAh, oAl);
        } else {
            bn_apply_f32<<<(NODES * HID / 4 + 255) / 256, 256>>>((float*)d_out);
        }
    }
}

// round 7
// speedup vs baseline: 2.4665x; 1.0138x over previous
#include <cuda_runtime.h>
#include <cuda_bf16.h>
#include <cstdint>

#define NODES 50000
#define MPAD  50176          // 196 * 256
#define EDIM  128
#define PDIM  768
#define HID   256
#define NREL  16
#define NEDGE 400000
#define BN_EPS 1e-5f
#define MBLK  196            // MPAD / 256
#define SCANB 196
#define PADR  (MPAD - NODES) // 176

// ---------------------------------------------------------------------------
// scratch (static device memory; no allocations)
// ---------------------------------------------------------------------------
__device__ __nv_bfloat16 g_Ah0[(size_t)MPAD * PDIM];
__device__ __nv_bfloat16 g_Al0[(size_t)MPAD * PDIM];
__device__ __nv_bfloat16 g_Ah1[(size_t)MPAD * PDIM];
__device__ __nv_bfloat16 g_Al1[(size_t)MPAD * PDIM];
__device__ __nv_bfloat16 g_Bth[3 * 256 * 768];
__device__ __nv_bfloat16 g_Btl[3 * 256 * 768];
__device__ float g_h0[(size_t)MPAD * HID];
__device__ float g_h1[(size_t)MPAD * HID];
__device__ float g_buf[(size_t)MPAD * HID];
__device__ int   g_cnt[NODES * NREL];
__device__ int   g_cntnode[NODES];
__device__ int   g_fill[NODES];
__device__ int   g_rowptr[NODES + 1];
__device__ int   g_blksum[SCANB];
__device__ int   g_packed[NEDGE];
__device__ float g_invw[NEDGE];
__device__ float g_sum[HID], g_sumsq[HID], g_scale[HID], g_shift[HID];

// ---------------------------------------------------------------------------
// helpers
// ---------------------------------------------------------------------------
__device__ __forceinline__ uint32_t smem_u32(const void* p) {
    uint32_t a;
    asm("{ .reg .u64 t; cvta.to.shared.u64 t, %1; cvt.u32.u64 %0, t; }" : "=r"(a) : "l"(p));
    return a;
}
__device__ __forceinline__ void cp16(uint32_t dst, const void* src) {
    asm volatile("cp.async.cg.shared.global [%0], [%1], 16;" :: "r"(dst), "l"(src) : "memory");
}
__device__ __forceinline__ void ldsm4(uint32_t* r, uint32_t addr) {
    asm volatile("ldmatrix.sync.aligned.m8n8.x4.shared.b16 {%0,%1,%2,%3}, [%4];"
                 : "=r"(r[0]), "=r"(r[1]), "=r"(r[2]), "=r"(r[3]) : "r"(addr));
}
__device__ __forceinline__ void mma16816(float* c, const uint32_t* a, const uint32_t* b) {
    asm volatile("mma.sync.aligned.m16n8k16.row.col.f32.bf16.bf16.f32 "
                 "{%0,%1,%2,%3}, {%4,%5,%6,%7}, {%8,%9}, {%0,%1,%2,%3};"
                 : "+f"(c[0]), "+f"(c[1]), "+f"(c[2]), "+f"(c[3])
                 : "r"(a[0]), "r"(a[1]), "r"(a[2]), "r"(a[3]), "r"(b[0]), "r"(b[1]));
}
static __device__ __forceinline__ uint32_t pack_bf2(float a, float b) {
    __nv_bfloat162 t;
    t.x = __float2bfloat16_rn(a);
    t.y = __float2bfloat16_rn(b);
    return *reinterpret_cast<uint32_t*>(&t);
}

#define ROWB    144
#define A_MAT   36864
#define B_MAT   18432
#define B_BASE  73728
#define STAGEB  110592
#define SMEM_GEMM (2 * STAGEB)

// ---------------------------------------------------------------------------
// split-bf16 GEMM via mma.sync: C = A @ B^T (+bias)
// CTA tile 256x128, 512 threads, warp tile 64x32, K-chunk 64, 2-stage cp.async
// GRID: blockIdx.x = (z*nbz + y) output-tile index (FASTEST -> A shared in L2),
//       blockIdx.y = row block
// ---------------------------------------------------------------------------
__device__ __forceinline__ void load_stage(
    uint32_t sb, int stage, int k0,
    const __nv_bfloat16* __restrict__ Ah, const __nv_bfloat16* __restrict__ Al,
    const __nv_bfloat16* __restrict__ Bh, const __nv_bfloat16* __restrict__ Bl,
    int K, int t)
{
    uint32_t base = sb + stage * STAGEB;
#pragma unroll
    for (int i = 0; i < 4; i++) {
        int unit = t + i * 512;
        int r = unit >> 3, u = unit & 7;
        uint32_t off = r * ROWB + u * 16;
        cp16(base + off,         Ah + (size_t)r * K + k0 + u * 8);
        cp16(base + A_MAT + off, Al + (size_t)r * K + k0 + u * 8);
    }
#pragma unroll
    for (int i = 0; i < 2; i++) {
        int unit = t + i * 512;
        int r = unit >> 3, u = unit & 7;
        uint32_t off = r * ROWB + u * 16;
        cp16(base + B_BASE + off,         Bh + (size_t)r * K + k0 + u * 8);
        cp16(base + B_BASE + B_MAT + off, Bl + (size_t)r * K + k0 + u * 8);
    }
    asm volatile("cp.async.commit_group;" ::: "memory");
}

__global__ void __launch_bounds__(512, 1) gemm_mma(
    const __nv_bfloat16* __restrict__ Ah, const __nv_bfloat16* __restrict__ Al,
    int K, int nbz,
    const __nv_bfloat16* __restrict__ Bth, const __nv_bfloat16* __restrict__ Btl,
    float* C0, float* C1, float* C2, int ldc,
    const float* bias0, const float* bias1, const float* bias2,
    __nv_bfloat16* Ch, __nv_bfloat16* Cl)
{
    extern __shared__ char smem[];
    uint32_t sb = smem_u32(smem);
    const int t = threadIdx.x;
    const int w = t >> 5, l = t & 31;
    const int wm = w >> 2, wn = w & 3;
    const int q = blockIdx.x;            // output-tile index, fastest-varying
    const int z = q / nbz;
    const int y = q - z * nbz;
    const int row0 = blockIdx.y * 256;
    const int col0 = y * 128;

    float* C = (z == 0) ? C0 : (z == 1) ? C1 : C2;
    const float* bias = (z == 0) ? bias0 : (z == 1) ? bias1 : bias2;

    const __nv_bfloat16* A_h = Ah + (size_t)row0 * K;
    const __nv_bfloat16* A_l = Al + (size_t)row0 * K;
    size_t Boff = (size_t)q * 128 * K;
    const __nv_bfloat16* B_h = Bth + Boff;
    const __nv_bfloat16* B_l = Btl + Boff;

    const uint32_t aoff = (uint32_t)((wm * 64 + (l & 15)) * ROWB + (l >> 4) * 16);
    const uint32_t boff = (uint32_t)((wn * 32 + (l & 7) + ((l >> 4) & 1) * 8) * ROWB
                                     + ((l >> 3) & 1) * 16);

    float acc[4][4][4];
#pragma unroll
    for (int mt = 0; mt < 4; mt++)
#pragma unroll
        for (int nt = 0; nt < 4; nt++)
#pragma unroll
            for (int j = 0; j < 4; j++) acc[mt][nt][j] = 0.f;

    const int nch = K >> 6;
    load_stage(sb, 0, 0, A_h, A_l, B_h, B_l, K, t);

    for (int c = 0; c < nch; c++) {
        if (c + 1 < nch) {
            load_stage(sb, (c + 1) & 1, (c + 1) << 6, A_h, A_l, B_h, B_l, K, t);
            asm volatile("cp.async.wait_group 1;" ::: "memory");
        } else {
            asm volatile("cp.async.wait_group 0;" ::: "memory");
        }
        __syncthreads();

        uint32_t Abase = sb + (c & 1) * STAGEB;
        uint32_t Bbase = Abase + B_BASE;
#pragma unroll
        for (int ks = 0; ks < 4; ks++) {
            uint32_t bh[2][4], bl[2][4];
#pragma unroll
            for (int p = 0; p < 2; p++) {
                ldsm4(bh[p], Bbase + boff + p * 2304 + ks * 32);
                ldsm4(bl[p], Bbase + B_MAT + boff + p * 2304 + ks * 32);
            }
#pragma unroll
            for (int mt = 0; mt < 4; mt++) {
                uint32_t ah[4], al[4];
                ldsm4(ah, Abase + aoff + mt * 2304 + ks * 32);
                ldsm4(al, Abase + A_MAT + aoff + mt * 2304 + ks * 32);
#pragma unroll
                for (int nt = 0; nt < 4; nt++) {
                    float* cc = acc[mt][nt];
                    const uint32_t* bph = &bh[nt >> 1][(nt & 1) * 2];
                    const uint32_t* bpl = &bl[nt >> 1][(nt & 1) * 2];
                    mma16816(cc, ah, bph);
                    mma16816(cc, al, bph);
                    mma16816(cc, ah, bpl);
                }
            }
        }
        __syncthreads();
    }

    const int rl = l >> 2;
    const int cl = (l & 3) * 2;
#pragma unroll
    for (int mt = 0; mt < 4; mt++) {
#pragma unroll
        for (int rh = 0; rh < 2; rh++) {
            int r = row0 + wm * 64 + mt * 16 + rh * 8 + rl;
#pragma unroll
            for (int nt = 0; nt < 4; nt++) {
                int cix = col0 + wn * 32 + nt * 8 + cl;
                float v0 = acc[mt][nt][rh * 2 + 0];
                float v1 = acc[mt][nt][rh * 2 + 1];
                if (bias) { v0 += bias[cix]; v1 += bias[cix + 1]; }
                if (C) {
                    *(float2*)(C + (size_t)r * ldc + cix) = make_float2(v0, v1);
                } else {
                    __nv_bfloat16 h0 = __float2bfloat16_rn(v0);
                    __nv_bfloat16 h1 = __float2bfloat16_rn(v1);
                    size_t ui = ((size_t)r * ldc + cix) >> 1;
                    __nv_bfloat162 hp; hp.x = h0; hp.y = h1;
                    ((uint32_t*)Ch)[ui] = *reinterpret_cast<uint32_t*>(&hp);
                    ((uint32_t*)Cl)[ui] = pack_bf2(v0 - __bfloat162float(h0),
                                                   v1 - __bfloat162float(h1));
                }
            }
        }
    }
}

// ---------------------------------------------------------------------------
// producers
// ---------------------------------------------------------------------------
__global__ void norm_split(const float* __restrict__ emb,
                           __nv_bfloat16* __restrict__ Ah, __nv_bfloat16* __restrict__ Al) {
    int gw = (blockIdx.x * blockDim.x + threadIdx.x) >> 5;
    if (gw >= NODES) return;
    int lane = threadIdx.x & 31;
    float4 v = ((const float4*)(emb + (size_t)gw * EDIM))[lane];
    float ss = v.x * v.x + v.y * v.y + v.z * v.z + v.w * v.w;
#pragma unroll
    for (int o = 16; o > 0; o >>= 1) ss += __shfl_xor_sync(0xffffffffu, ss, o);
    float inv = 1.0f / fmaxf(sqrtf(ss), 1e-12f);
    v.x *= inv; v.y *= inv; v.z *= inv; v.w *= inv;
    __nv_bfloat16 hx = __float2bfloat16_rn(v.x), hy = __float2bfloat16_rn(v.y);
    __nv_bfloat16 hz = __float2bfloat16_rn(v.z), hw = __float2bfloat16_rn(v.w);
    size_t ui = ((size_t)gw * EDIM + lane * 4) >> 1;
    __nv_bfloat162 p0; p0.x = hx; p0.y = hy;
    __nv_bfloat162 p1; p1.x = hz; p1.y = hw;
    ((uint32_t*)Ah)[ui]     = *reinterpret_cast<uint32_t*>(&p0);
    ((uint32_t*)Ah)[ui + 1] = *reinterpret_cast<uint32_t*>(&p1);
    ((uint32_t*)Al)[ui]     = pack_bf2(v.x - __bfloat162float(hx), v.y - __bfloat162float(hy));
    ((uint32_t*)Al)[ui + 1] = pack_bf2(v.z - __bfloat162float(hz), v.w - __bfloat162float(hw));
}

__global__ void zero_pads_all() {
    const int Ks[4] = {128, 256, 768, 256};
    int reg = blockIdx.y;
    int K = Ks[reg];
    int n = PADR * K / 2;
    int i = blockIdx.x * blockDim.x + threadIdx.x;
    if (i >= n) return;
    size_t base = (size_t)NODES * K / 2;
    if (reg < 2) {
        ((uint32_t*)g_Ah0)[base + i] = 0;
        ((uint32_t*)g_Al0)[base + i] = 0;
    } else {
        ((uint32_t*)g_Ah1)[base + i] = 0;
        ((uint32_t*)g_Al1)[base + i] = 0;
    }
}

__global__ void split_bt_proj(const float* __restrict__ W) {
    int idx = blockIdx.x * blockDim.x + threadIdx.x;
    if (idx >= EDIM * PDIM) return;
    int k = idx / PDIM, n = idx % PDIM;
    float v = W[idx];
    __nv_bfloat16 h = __float2bfloat16_rn(v);
    g_Bth[(size_t)n * EDIM + k] = h;
    g_Btl[(size_t)n * EDIM + k] = __float2bfloat16_rn(v - __bfloat162float(h));
}

__global__ void split_bt_layer(const float* __restrict__ bases, const float* __restrict__ root, int K) {
    int z = blockIdx.z;
    int idx = blockIdx.x * blockDim.x + threadIdx.x;
    if (z == 0 && blockIdx.x == 0 && threadIdx.x < HID) {
        g_sum[threadIdx.x] = 0.f;
        g_sumsq[threadIdx.x] = 0.f;
    }
    const float* in = (z < 2) ? bases + (size_t)z * K * HID : root;
    if (idx >= K * HID) return;
    int k = idx / HID, n = idx % HID;
    float v = in[idx];
    __nv_bfloat16 h = __float2bfloat16_rn(v);
    size_t o = ((size_t)z * HID + n) * K + k;
    g_Bth[o] = h;
    g_Btl[o] = __float2bfloat16_rn(v - __bfloat162float(h));
}

// ---------------------------------------------------------------------------
// CSR build
// ---------------------------------------------------------------------------
__global__ void zero_counts() {
    int i = blockIdx.x * blockDim.x + threadIdx.x;
    if (i < NODES * NREL) g_cnt[i] = 0;
    if (i < NODES) { g_cntnode[i] = 0; g_fill[i] = 0; }
}
__global__ void count_edges(const int* __restrict__ dst, const int* __restrict__ et) {
    int e = blockIdx.x * blockDim.x + threadIdx.x;
    if (e < NEDGE) {
        int d = dst[e];
        atomicAdd(&g_cnt[d * NREL + et[e]], 1);
        atomicAdd(&g_cntnode[d], 1);
    }
}
__global__ void scan1() {
    __shared__ int sh[256];
    int t = threadIdx.x;
    int idx = blockIdx.x * 256 + t;
    int v = (idx < NODES) ? g_cntnode[idx] : 0;
    sh[t] = v;
    __syncthreads();
#pragma unroll
    for (int o = 1; o < 256; o <<= 1) {
        int x = (t >= o) ? sh[t - o] : 0;
        __syncthreads();
        sh[t] += x;
        __syncthreads();
    }
    if (idx < NODES) g_rowptr[idx + 1] = sh[t];
    if (t == 255) g_blksum[blockIdx.x] = sh[255];
}
__global__ void scan2() {    // single warp, shfl-based scan of SCANB block sums
    int t = threadIdx.x;     // 32 threads
    int carry = 0;
    for (int base = 0; base < SCANB; base += 32) {
        int idx = base + t;
        int vin = (idx < SCANB) ? g_blksum[idx] : 0;
        int v = vin;
#pragma unroll
        for (int o = 1; o < 32; o <<= 1) {
            int x = __shfl_up_sync(0xffffffffu, v, o);
            if (t >= o) v += x;
        }
        if (idx < SCANB) g_blksum[idx] = carry + v - vin;   // exclusive
        carry += __shfl_sync(0xffffffffu, v, 31);
    }
    if (t == 0) g_rowptr[0] = 0;
}
__global__ void scan3() {
    int idx = blockIdx.x * blockDim.x + threadIdx.x;
    if (idx < NODES) g_rowptr[idx + 1] += g_blksum[idx >> 8];
}
__global__ void scatter_edges(const int* __restrict__ src, const int* __restrict__ dst,
                              const int* __restrict__ et) {
    int e = blockIdx.x * blockDim.x + threadIdx.x;
    if (e >= NEDGE) return;
    int d = dst[e], r = et[e], s = src[e];
    int pos = g_rowptr[d] + atomicAdd(&g_fill[d], 1);
    g_packed[pos] = s | (r << 24);
    int c = g_cnt[d * NREL + r];
    g_invw[pos] = 1.0f / (float)(c > 0 ? c : 1);
}

// ---------------------------------------------------------------------------
// gather aggregation + fused BN statistics
// ---------------------------------------------------------------------------
#define AGG_BLOCKS 1184
__global__ void __launch_bounds__(256) csr_agg_bn(const float* __restrict__ comp) {
    __shared__ float s_sum[HID];
    __shared__ float s_sumsq[HID];
    __shared__ float s_comp[2 * NREL];
    int t = threadIdx.x;
    if (t < 2 * NREL) s_comp[t] = comp[t];
    s_sum[t] = 0.f;
    s_sumsq[t] = 0.f;
    __syncthreads();

    int lane = t & 31, wid = t >> 5;
    float bsum[8], bsq[8];
#pragma unroll
    for (int i = 0; i < 8; i++) { bsum[i] = 0.f; bsq[i] = 0.f; }

    for (int d = blockIdx.x * 8 + wid; d < NODES; d += AGG_BLOCKS * 8) {
        int beg = g_rowptr[d], end = g_rowptr[d + 1];
        float* bp = &g_buf[(size_t)d * HID];
        float4 acc0 = ((float4*)bp)[lane];
        float4 acc1 = ((float4*)bp)[lane + 32];
        for (int e = beg; e < end; e++) {
            int pk = __ldg(&g_packed[e]);
            float w = __ldg(&g_invw[e]);
            int s = pk & 0xFFFFFF;
            int r = pk >> 24;
            float c0 = s_comp[2 * r] * w;
            float c1 = s_comp[2 * r + 1] * w;
            const float4* h0p = (const float4*)&g_h0[(size_t)s * HID];
            const float4* h1p = (const float4*)&g_h1[(size_t)s * HID];
            float4 a0 = h0p[lane],      b0 = h1p[lane];
            float4 a1 = h0p[lane + 32], b1 = h1p[lane + 32];
            acc0.x += c0 * a0.x + c1 * b0.x;
            acc0.y += c0 * a0.y + c1 * b0.y;
            acc0.z += c0 * a0.z + c1 * b0.z;
            acc0.w += c0 * a0.w + c1 * b0.w;
            acc1.x += c0 * a1.x + c1 * b1.x;
            acc1.y += c0 * a1.y + c1 * b1.y;
            acc1.z += c0 * a1.z + c1 * b1.z;
            acc1.w += c0 * a1.w + c1 * b1.w;
        }
        ((float4*)bp)[lane] = acc0;
        ((float4*)bp)[lane + 32] = acc1;
        bsum[0] += acc0.x; bsq[0] += acc0.x * acc0.x;
        bsum[1] += acc0.y; bsq[1] += acc0.y * acc0.y;
        bsum[2] += acc0.z; bsq[2] += acc0.z * acc0.z;
        bsum[3] += acc0.w; bsq[3] += acc0.w * acc0.w;
        bsum[4] += acc1.x; bsq[4] += acc1.x * acc1.x;
        bsum[5] += acc1.y; bsq[5] += acc1.y * acc1.y;
        bsum[6] += acc1.z; bsq[6] += acc1.z * acc1.z;
        bsum[7] += acc1.w; bsq[7] += acc1.w * acc1.w;
    }

#pragma unroll
    for (int i = 0; i < 4; i++) {
        atomicAdd(&s_sum[lane * 4 + i], bsum[i]);
        atomicAdd(&s_sumsq[lane * 4 + i], bsq[i]);
        atomicAdd(&s_sum[128 + lane * 4 + i], bsum[4 + i]);
        atomicAdd(&s_sumsq[128 + lane * 4 + i], bsq[4 + i]);
    }
    __syncthreads();
    atomicAdd(&g_sum[t], s_sum[t]);
    atomicAdd(&g_sumsq[t], s_sumsq[t]);
}

// ---------------------------------------------------------------------------
// batchnorm finalize + apply
// ---------------------------------------------------------------------------
__global__ void bn_finalize(const float* __restrict__ gamma, const float* __restrict__ beta) {
    int c = threadIdx.x;
    const float invM = 1.0f / (float)NODES;
    float mean = g_sum[c] * invM;
    float var = g_sumsq[c] * invM - mean * mean;
    float sc = gamma[c] * rsqrtf(var + BN_EPS);
    g_scale[c] = sc;
    g_shift[c] = beta[c] - mean * sc;
}
__global__ void bn_apply_f32(float* __restrict__ out) {
    int idx = blockIdx.x * blockDim.x + threadIdx.x;
    if (idx >= NODES * HID / 4) return;
    int c4 = (idx & 63) << 2;
    float4 v = ((const float4*)g_buf)[idx];
    float4 sc = *(const float4*)&g_scale[c4];
    float4 sh = *(const float4*)&g_shift[c4];
    v.x = fmaxf(fmaf(v.x, sc.x, sh.x), 0.f);
    v.y = fmaxf(fmaf(v.y, sc.y, sh.y), 0.f);
    v.z = fmaxf(fmaf(v.z, sc.z, sh.z), 0.f);
    v.w = fmaxf(fmaf(v.w, sc.w, sh.w), 0.f);
    ((float4*)out)[idx] = v;
}
__global__ void bn_apply_split(__nv_bfloat16* __restrict__ Ah, __nv_bfloat16* __restrict__ Al) {
    int idx = blockIdx.x * blockDim.x + threadIdx.x;
    if (idx >= NODES * HID / 4) return;
    int c4 = (idx & 63) << 2;
    float4 v = ((const float4*)g_buf)[idx];
    float4 sc = *(const float4*)&g_scale[c4];
    float4 sh = *(const float4*)&g_shift[c4];
    v.x = fmaxf(fmaf(v.x, sc.x, sh.x), 0.f);
    v.y = fmaxf(fmaf(v.y, sc.y, sh.y), 0.f);
    v.z = fmaxf(fmaf(v.z, sc.z, sh.z), 0.f);
    v.w = fmaxf(fmaf(v.w, sc.w, sh.w), 0.f);
    __nv_bfloat16 hx = __float2bfloat16_rn(v.x), hy = __float2bfloat16_rn(v.y);
    __nv_bfloat16 hz = __float2bfloat16_rn(v.z), hw = __float2bfloat16_rn(v.w);
    __nv_bfloat162 p0; p0.x = hx; p0.y = hy;
    __nv_bfloat162 p1; p1.x = hz; p1.y = hw;
    ((uint32_t*)Ah)[idx * 2]     = *reinterpret_cast<uint32_t*>(&p0);
    ((uint32_t*)Ah)[idx * 2 + 1] = *reinterpret_cast<uint32_t*>(&p1);
    ((uint32_t*)Al)[idx * 2]     = pack_bf2(v.x - __bfloat162float(hx), v.y - __bfloat162float(hy));
    ((uint32_t*)Al)[idx * 2 + 1] = pack_bf2(v.z - __bfloat162float(hz), v.w - __bfloat162float(hw));
}

// ---------------------------------------------------------------------------
// host launch
// ---------------------------------------------------------------------------
extern "C" void kernel_launch(void* const* d_in, const int* in_sizes, int n_in,
                              void* d_out, int out_size) {
    const int* edge_index = (const int*)d_in[0];
    const int* src = edge_index;
    const int* dst = edge_index + NEDGE;
    const int* etype = (const int*)d_in[1];
    const float* emb = (const float*)d_in[2];
    const float* proj_w = (const float*)d_in[3];
    const float* proj_b = (const float*)d_in[4];

    const float *comp[3], *bases[3], *root[3], *bias[3], *gamma[3], *beta[3];
    for (int l = 0; l < 3; l++) {
        comp[l]  = (const float*)d_in[5 + 6 * l];
        bases[l] = (const float*)d_in[6 + 6 * l];
        root[l]  = (const float*)d_in[7 + 6 * l];
        bias[l]  = (const float*)d_in[8 + 6 * l];
        gamma[l] = (const float*)d_in[9 + 6 * l];
        beta[l]  = (const float*)d_in[10 + 6 * l];
    }

    __nv_bfloat16 *Ah0, *Al0, *Ah1, *Al1, *Bth, *Btl;
    float *h0, *h1, *buf;
    cudaGetSymbolAddress((void**)&Ah0, g_Ah0);
    cudaGetSymbolAddress((void**)&Al0, g_Al0);
    cudaGetSymbolAddress((void**)&Ah1, g_Ah1);
    cudaGetSymbolAddress((void**)&Al1, g_Al1);
    cudaGetSymbolAddress((void**)&Bth, g_Bth);
    cudaGetSymbolAddress((void**)&Btl, g_Btl);
    cudaGetSymbolAddress((void**)&h0, g_h0);
    cudaGetSymbolAddress((void**)&h1, g_h1);
    cudaGetSymbolAddress((void**)&buf, g_buf);

    cudaFuncSetAttribute(gemm_mma, cudaFuncAttributeMaxDynamicSharedMemorySize, SMEM_GEMM);

    // launches 1-3: producers for proj GEMM
    norm_split<<<(NODES * 32 + 255) / 256, 256>>>(emb, Ah0, Al0);
    {
        dim3 g((PADR * 768 / 2 + 255) / 256, 4);
        zero_pads_all<<<g, 256>>>();
    }
    split_bt_proj<<<(EDIM * PDIM + 255) / 256, 256>>>(proj_w);

    // launch 4: proj GEMM (ncu capture target) — q fastest for A reuse in L2
    {
        dim3 grid(6, MBLK);
        gemm_mma<<<grid, 512, SMEM_GEMM>>>(
            Ah0, Al0, EDIM, 6, Bth, Btl,
            nullptr, nullptr, nullptr, PDIM,
            proj_b, proj_b, proj_b,
            Ah1, Al1);
    }

    // CSR build (independent of GEMM chain)
    zero_counts<<<(NODES * NREL + 255) / 256, 256>>>();
    count_edges<<<(NEDGE + 255) / 256, 256>>>(dst, etype);
    scan1<<<SCANB, 256>>>();
    scan2<<<1, 32>>>();
    scan3<<<(NODES + 255) / 256, 256>>>();
    scatter_edges<<<(NEDGE + 255) / 256, 256>>>(src, dst, etype);

    for (int l = 0; l < 3; l++) {
        int K = (l == 0) ? PDIM : HID;
        __nv_bfloat16* Ah = (l == 1) ? Ah0 : Ah1;
        __nv_bfloat16* Al = (l == 1) ? Al0 : Al1;

        {
            dim3 g((K * HID + 255) / 256, 1, 3);
            split_bt_layer<<<g, 256>>>(bases[l], root[l], K);   // also zeroes BN stats
        }
        {
            dim3 grid(6, MBLK);     // q = z*2+y fastest -> A reuse
            gemm_mma<<<grid, 512, SMEM_GEMM>>>(
                Ah, Al, K, 2, Bth, Btl,
                h0, h1, buf, HID,
                nullptr, nullptr, bias[l],
                nullptr, nullptr);
        }
        csr_agg_bn<<<AGG_BLOCKS, 256>>>(comp[l]);
        bn_finalize<<<1, HID>>>(gamma[l], beta[l]);
        if (l < 2) {
            __nv_bfloat16* oAh = (l == 0) ? Ah0 : Ah1;
            __nv_bfloat16* oAl = (l == 0) ? Al0 : Al1;
            bn_apply_split<<<(NODES * HID / 4 + 255) / 256, 256>>>(oAh, oAl);
        } else {
            bn_apply_f32<<<(NODES * HID / 4 + 255) / 256, 256>>>((float*)d_out);
        }
    }
}